// round 11
// baseline (speedup 1.0000x reference)
#include <cuda_runtime.h>
#include <math.h>
#include <stdint.h>

#define BATCH 2
#define SEQ 2048
#define HIDDEN 2048
#define NH 16
#define KVH 4
#define HD 128
#define MTOT (BATCH*SEQ)
#define QKVW 3072
#define KOFF 2048
#define VOFF 2560

// scratch (no allocation allowed -> device globals)
__device__ float g_qkv[MTOT*QKVW];
__device__ float g_ctx[MTOT*HIDDEN];
__device__ float g_hs[MTOT*HIDDEN];
__device__ float g_wqkv[QKVW*HIDDEN];
__device__ float g_wo[HIDDEN*HIDDEN];

// ===========================================================================
// helpers
// ===========================================================================
__device__ __forceinline__ uint32_t smem_u32(const void* p) {
    uint32_t a;
    asm("{ .reg .u64 t; cvta.to.shared.u64 t, %1; cvt.u32.u64 %0, t; }"
        : "=r"(a) : "l"(p));
    return a;
}
__device__ __forceinline__ void cp_async16(uint32_t saddr, const void* gaddr) {
    asm volatile("cp.async.cg.shared.global [%0], [%1], 16;"
                 :: "r"(saddr), "l"(gaddr));
}
__device__ __forceinline__ void cp_commit() {
    asm volatile("cp.async.commit_group;" ::: "memory");
}
__device__ __forceinline__ void cp_wait1() {
    asm volatile("cp.async.wait_group 1;" ::: "memory");
}
__device__ __forceinline__ void cp_wait0() {
    asm volatile("cp.async.wait_group 0;" ::: "memory");
}
__device__ __forceinline__ float tf32_round(float x) {
    uint32_t u;
    asm("cvt.rna.tf32.f32 %0, %1;" : "=r"(u) : "f"(x));
    return __uint_as_float(u);
}
__device__ __forceinline__ void mma_tf32(float* d, const uint32_t* a, const uint32_t* b) {
    asm volatile(
        "mma.sync.aligned.m16n8k8.row.col.f32.tf32.tf32.f32 "
        "{%0,%1,%2,%3}, {%4,%5,%6,%7}, {%8,%9}, {%0,%1,%2,%3};"
        : "+f"(d[0]), "+f"(d[1]), "+f"(d[2]), "+f"(d[3])
        : "r"(a[0]), "r"(a[1]), "r"(a[2]), "r"(a[3]), "r"(b[0]), "r"(b[1]));
}
#define LDSM4(r0,r1,r2,r3,addr)                                              \
    asm volatile("ldmatrix.sync.aligned.m8n8.x4.shared.b16 {%0,%1,%2,%3}, [%4];" \
        : "=r"(r0), "=r"(r1), "=r"(r2), "=r"(r3) : "r"(addr))

// ===========================================================================
// fused tf32 rounding pass: hs -> g_hs, [Wq|Wk|Wv] -> g_wqkv, Wo -> g_wo
// ===========================================================================
#define N4_HS  (MTOT*HIDDEN/4)
#define N4_WQ  (HIDDEN*HIDDEN/4)
#define N4_WKV (KVH*HD*HIDDEN/4)
#define N4_TOT (N4_HS + 2*N4_WQ + 2*N4_WKV)

__global__ void round5_kernel(
    const float* __restrict__ hs, const float* __restrict__ wq,
    const float* __restrict__ wk, const float* __restrict__ wv,
    const float* __restrict__ wo,
    float* __restrict__ dhs, float* __restrict__ dwqkv,
    float* __restrict__ dwo)
{
    int i = blockIdx.x * 256 + threadIdx.x;
    if (i >= N4_TOT) return;
    const float* src; float* dst; int j = i;
    if (j < N4_HS)                  { src = hs; dst = dhs; }
    else if ((j -= N4_HS) < N4_WQ)  { src = wq; dst = dwqkv; }
    else if ((j -= N4_WQ) < N4_WKV) { src = wk; dst = dwqkv + (size_t)KOFF*HIDDEN; }
    else if ((j -= N4_WKV) < N4_WKV){ src = wv; dst = dwqkv + (size_t)VOFF*HIDDEN; }
    else { j -= N4_WKV; src = wo; dst = dwo; }
    float4 v = ((const float4*)src)[j];
    v.x = tf32_round(v.x); v.y = tf32_round(v.y);
    v.z = tf32_round(v.z); v.w = tf32_round(v.w);
    ((float4*)dst)[j] = v;
}

// ===========================================================================
// tf32 mma.sync GEMM with ldmatrix. CTA 128x256, BK=32, 3-stage cp.async,
// 512 threads (16 warps, 2x8 grid, warp tile 64x32). N multiple of 256.
// ===========================================================================
#define BK 32
#define APAD 36
#define STAGE_FLOATS ((128+256)*APAD)
#define NSTAGE 3
#define GEMM_SMEM (NSTAGE*STAGE_FLOATS*4)

__global__ void __launch_bounds__(512, 1) gemm_mma(
    const float* __restrict__ A, const float* __restrict__ B,
    float* __restrict__ C, int M, int N, int K)
{
    extern __shared__ float sm[];
    const uint32_t smb = smem_u32(sm);

    const int tid  = threadIdx.x;
    const int warp = tid >> 5, lane = tid & 31;
    const int wm = warp >> 3, wn = warp & 7;
    const int m0 = blockIdx.y << 7, n0 = blockIdx.x << 8;
    const int q = lane >> 2, r = lane & 3;

    const int lmt = lane >> 3, lmr = lane & 7;
    const uint32_t lmoff = (uint32_t)((((lmt & 1) << 3 | lmr) * APAD + ((lmt >> 1) << 2)) * 4);

    float acc[4][4][4];
#pragma unroll
    for (int i = 0; i < 4; i++)
#pragma unroll
        for (int j = 0; j < 4; j++)
            acc[i][j][0]=acc[i][j][1]=acc[i][j][2]=acc[i][j][3]=0.f;

    const int arow0 = tid >> 3, ach = (tid & 7) << 2;

#define LOAD_TILE(s, kt) do {                                               \
    const uint32_t sA_ = smb + (uint32_t)(s)*STAGE_FLOATS*4;                \
    const uint32_t sB_ = sA_ + 128*APAD*4;                                  \
    const int koff = (kt) * BK;                                             \
    _Pragma("unroll")                                                       \
    for (int l_ = 0; l_ < 2; l_++) {                                        \
        int row = arow0 + l_*64;                                            \
        cp_async16(sA_ + (uint32_t)(row*APAD + ach)*4,                      \
                   A + (size_t)(m0 + row) * K + koff + ach);                \
    }                                                                       \
    _Pragma("unroll")                                                       \
    for (int l_ = 0; l_ < 4; l_++) {                                        \
        int row = arow0 + l_*64;                                            \
        cp_async16(sB_ + (uint32_t)(row*APAD + ach)*4,                      \
                   B + (size_t)(n0 + row) * K + koff + ach);                \
    } } while (0)

    const int KT = K / BK;
    LOAD_TILE(0, 0); cp_commit();
    LOAD_TILE(1, 1); cp_commit();
    cp_wait1();
    __syncthreads();

    for (int kt = 0; kt < KT; kt++) {
        const int nxt = kt + 2;
        if (nxt < KT) {
            int s = nxt - (nxt/NSTAGE)*NSTAGE;
            LOAD_TILE(s, nxt);
        }
        cp_commit();

        const int cs = kt - (kt/NSTAGE)*NSTAGE;
        const uint32_t sAb = smb + (uint32_t)cs*STAGE_FLOATS*4;
        const uint32_t sBb = sAb + 128*APAD*4;

#pragma unroll
        for (int ks = 0; ks < 4; ks++) {
            const int kk = ks * 8;
            uint32_t afr[4][4], bfr[4][2];
#pragma unroll
            for (int i = 0; i < 4; i++)
                LDSM4(afr[i][0], afr[i][1], afr[i][2], afr[i][3],
                      sAb + (uint32_t)(((wm*64 + i*16)*APAD + kk)*4) + lmoff);
            LDSM4(bfr[0][0], bfr[1][0], bfr[0][1], bfr[1][1],
                  sBb + (uint32_t)(((wn*32)*APAD + kk)*4) + lmoff);
            LDSM4(bfr[2][0], bfr[3][0], bfr[2][1], bfr[3][1],
                  sBb + (uint32_t)(((wn*32 + 16)*APAD + kk)*4) + lmoff);
#pragma unroll
            for (int i = 0; i < 4; i++)
#pragma unroll
                for (int j = 0; j < 4; j++)
                    mma_tf32(acc[i][j], afr[i], bfr[j]);
        }

        cp_wait1();
        __syncthreads();
    }

#pragma unroll
    for (int i = 0; i < 4; i++) {
        const int row = m0 + wm*64 + i*16 + q;
#pragma unroll
        for (int j = 0; j < 4; j++) {
            const int col = n0 + wn*32 + j*8 + 2*r;
            float2 lo; lo.x = acc[i][j][0]; lo.y = acc[i][j][1];
            float2 hi; hi.x = acc[i][j][2]; hi.y = acc[i][j][3];
            *(float2*)(C + (size_t)row * N + col)       = lo;
            *(float2*)(C + (size_t)(row+8) * N + col)   = hi;
        }
    }
#undef LOAD_TILE
}

// ---------------------------------------------------------------------------
// fused RoPE + tf32 rounding: q (rope+round), k (rope+round), v (round only)
// ---------------------------------------------------------------------------
#define ROPE_NQ (MTOT*NH*64)
#define ROPE_NK (MTOT*KVH*64)
#define ROPE_NV (MTOT*128)
#define ROPE_TOT (ROPE_NQ + ROPE_NK + ROPE_NV)

__global__ void rope_round_kernel(float* __restrict__ qkv,
                                  const float* __restrict__ cs,
                                  const float* __restrict__ sn)
{
    int idx = blockIdx.x * 256 + threadIdx.x;
    if (idx < ROPE_NQ) {
        int d = idx & 63;
        int h = (idx >> 6) % NH;
        int t = idx / (NH << 6);
        float* row = qkv + (size_t)t * QKVW + h * HD;
        int s = t & (SEQ - 1);
        float x1 = row[d], x2 = row[d + 64];
        row[d]      = tf32_round(x1 * cs[s*HD + d]      - x2 * sn[s*HD + d]);
        row[d + 64] = tf32_round(x2 * cs[s*HD + d + 64] + x1 * sn[s*HD + d + 64]);
    } else if ((idx -= ROPE_NQ) < ROPE_NK) {
        int d = idx & 63;
        int h = (idx >> 6) % KVH;
        int t = idx / (KVH << 6);
        float* row = qkv + (size_t)t * QKVW + KOFF + h * HD;
        int s = t & (SEQ - 1);
        float x1 = row[d], x2 = row[d + 64];
        row[d]      = tf32_round(x1 * cs[s*HD + d]      - x2 * sn[s*HD + d]);
        row[d + 64] = tf32_round(x2 * cs[s*HD + d + 64] + x1 * sn[s*HD + d + 64]);
    } else if ((idx -= ROPE_NK) < ROPE_NV) {
        int t = idx >> 7, c4 = (idx & 127) << 2;
        float* p = qkv + (size_t)t * QKVW + VOFF + c4;
        float4 v = *(float4*)p;
        v.x = tf32_round(v.x); v.y = tf32_round(v.y);
        v.z = tf32_round(v.z); v.w = tf32_round(v.w);
        *(float4*)p = v;
    }
}

// ---------------------------------------------------------------------------
// Flash attention, mma.sync tf32 + ldmatrix. Br=128, Bc=128, D=128.
// 256 threads (8 warps, 2x4 grid, warp tile 64x32 in both loops -> 1.5 wf/MMA).
// sS overlaid on sK (K fully consumed into registers before sS is written).
// ---------------------------------------------------------------------------
#define FQKP 132
#define FSQ 0
#define FSK (128*FQKP)
#define FSV (FSK + 128*FQKP)
#define FSS FSK                      // overlay: scores reuse the K region
#define FSC (FSV + 128*FQKP)
#define FLASH_FLOATS (FSC + 128)
#define FLASH_SMEM (FLASH_FLOATS*4)

__global__ void __launch_bounds__(256, 1) flash_mma_kernel(
    const float* __restrict__ qkv, float* __restrict__ ctx)
{
    extern __shared__ float sm[];
    const uint32_t smb = smem_u32(sm);
    float* sS   = sm + FSS;
    float* scorr= sm + FSC;

    const int b = blockIdx.z, h = blockIdx.y;
    const int qb = (int)gridDim.x - 1 - (int)blockIdx.x;   // long CTAs first
    const int kh = h >> 2;
    const int tid = threadIdx.x;
    const int warp = tid >> 5, lane = tid & 31;
    const int wm = warp >> 2, wn = warp & 3;               // 2 x 4 warp grid
    const int qd = lane >> 2, r4 = lane & 3;

    const int lmt = lane >> 3, lmr = lane & 7;
    const int lmrow = ((lmt & 1) << 3) | lmr;
    const int lmcol = (lmt >> 1) << 2;
    const uint32_t lmQK = (uint32_t)((lmrow*FQKP + lmcol) * 4);

    // V transpose mapping: thread -> 4(j) x 4(d) blocks
    const int vj0 = (tid & 31) << 2;          // j0: 0..124
    const int vd0 = (tid >> 5) << 2;          // d0 base: 0..28, +l*32

    // ---- Q tile via cp.async (128 x 128) ----
    const float* qbase = qkv + (size_t)(b*SEQ + qb*128) * QKVW + h * HD;
#pragma unroll
    for (int l = 0; l < 16; l++) {
        int idx = tid + l*256;
        int row = idx >> 5, c4 = (idx & 31) << 2;
        cp_async16(smb + (uint32_t)((FSQ + row*FQKP + c4)*4),
                   qbase + (size_t)row * QKVW + c4);
    }
    cp_commit();

    float m_r[16], l_r[16];
#pragma unroll
    for (int i = 0; i < 16; i++) { m_r[i] = -1e30f; l_r[i] = 0.f; }

    float oacc[4][4][4];
#pragma unroll
    for (int i = 0; i < 4; i++)
#pragma unroll
        for (int j = 0; j < 4; j++)
            oacc[i][j][0]=oacc[i][j][1]=oacc[i][j][2]=oacc[i][j][3]=0.f;

    const int grow0 = qb * 128;
    const float sscale = 0.08838834764831845f;

    for (int jb = 0; jb <= qb; jb++) {
        __syncthreads();   // prior PV done with sS/sVt
        const float* kbase = qkv + (size_t)(b*SEQ + jb*128) * QKVW + KOFF + kh * HD;
        const float* vbase = qkv + (size_t)(b*SEQ + jb*128) * QKVW + VOFF + kh * HD;
        // K via cp.async (128 x 128) into sK (== sS region)
#pragma unroll
        for (int l = 0; l < 16; l++) {
            int idx = tid + l*256;
            int row = idx >> 5, c4 = (idx & 31) << 2;
            cp_async16(smb + (uint32_t)((FSK + row*FQKP + c4)*4),
                       kbase + (size_t)row * QKVW + c4);
        }
        cp_commit();
        // V transposed into sVt [d:128][j:128] stride 132 (conflict-free STS.128)
#pragma unroll
        for (int l = 0; l < 4; l++) {
            const int d0 = vd0 + l*32;
            float4 v0 = *(const float4*)(vbase + (size_t)(vj0+0) * QKVW + d0);
            float4 v1 = *(const float4*)(vbase + (size_t)(vj0+1) * QKVW + d0);
            float4 v2 = *(const float4*)(vbase + (size_t)(vj0+2) * QKVW + d0);
            float4 v3 = *(const float4*)(vbase + (size_t)(vj0+3) * QKVW + d0);
            float4 t;
            t.x=v0.x; t.y=v1.x; t.z=v2.x; t.w=v3.x;
            *(float4*)&sm[FSV + (d0+0)*FQKP + vj0] = t;
            t.x=v0.y; t.y=v1.y; t.z=v2.y; t.w=v3.y;
            *(float4*)&sm[FSV + (d0+1)*FQKP + vj0] = t;
            t.x=v0.z; t.y=v1.z; t.z=v2.z; t.w=v3.z;
            *(float4*)&sm[FSV + (d0+2)*FQKP + vj0] = t;
            t.x=v0.w; t.y=v1.w; t.z=v2.w; t.w=v3.w;
            *(float4*)&sm[FSV + (d0+3)*FQKP + vj0] = t;
        }
        cp_wait0();
        __syncthreads();

        // ---- QK: warp tile 64x32 at (wm*64, wn*32), 16 ks steps ----
        float sc[4][4][4];
#pragma unroll
        for (int i = 0; i < 4; i++)
#pragma unroll
            for (int j = 0; j < 4; j++)
                sc[i][j][0]=sc[i][j][1]=sc[i][j][2]=sc[i][j][3]=0.f;

        const uint32_t aQ0 = smb + (uint32_t)((FSQ + (wm*64)*FQKP)*4) + lmQK;
        const uint32_t bK0 = smb + (uint32_t)((FSK + (wn*32)*FQKP)*4) + lmQK;
#pragma unroll
        for (int ks = 0; ks < 16; ks++) {
            const uint32_t kk4 = (uint32_t)(ks*32);
            uint32_t qa[4][4], kb[4][2];
#pragma unroll
            for (int i = 0; i < 4; i++)
                LDSM4(qa[i][0], qa[i][1], qa[i][2], qa[i][3],
                      aQ0 + (uint32_t)(i*16*FQKP*4) + kk4);
            LDSM4(kb[0][0], kb[1][0], kb[0][1], kb[1][1], bK0 + kk4);
            LDSM4(kb[2][0], kb[3][0], kb[2][1], kb[3][1],
                  bK0 + (uint32_t)(16*FQKP*4) + kk4);
#pragma unroll
            for (int i = 0; i < 4; i++)
#pragma unroll
                for (int j = 0; j < 4; j++)
                    mma_tf32(sc[i][j], qa[i], kb[j]);
        }
        __syncthreads();   // all K reads done before sS overlays the region

        // store scaled scores to sS (overlaid on sK)
#pragma unroll
        for (int i = 0; i < 4; i++) {
            const int row = wm*64 + i*16 + qd;
#pragma unroll
            for (int j = 0; j < 4; j++) {
                const int col = wn*32 + j*8 + 2*r4;
                float2 lo; lo.x = sc[i][j][0]*sscale; lo.y = sc[i][j][1]*sscale;
                float2 hi; hi.x = sc[i][j][2]*sscale; hi.y = sc[i][j][3]*sscale;
                *(float2*)&sS[row*FQKP + col]     = lo;
                *(float2*)&sS[(row+8)*FQKP + col] = hi;
            }
        }
        __syncthreads();

        // ---- softmax (scalar fp32), warp owns rows warp*16..+15 ----
        const bool diag = (jb == qb);
        const int col0 = jb * 128;
#pragma unroll
        for (int rr = 0; rr < 16; rr++) {
            int row = warp*16 + rr;
            int grow = grow0 + row;
            float s0 = sS[row*FQKP + lane];
            float s1 = sS[row*FQKP + 32 + lane];
            float s2 = sS[row*FQKP + 64 + lane];
            float s3 = sS[row*FQKP + 96 + lane];
            if (diag) {
                if (col0 + lane > grow)      s0 = -1e30f;
                if (col0 + 32 + lane > grow) s1 = -1e30f;
                if (col0 + 64 + lane > grow) s2 = -1e30f;
                if (col0 + 96 + lane > grow) s3 = -1e30f;
            }
            float mx = fmaxf(fmaxf(s0, s1), fmaxf(s2, s3));
#pragma unroll
            for (int o = 16; o > 0; o >>= 1)
                mx = fmaxf(mx, __shfl_xor_sync(0xffffffffu, mx, o));
            float m_new = fmaxf(m_r[rr], mx);
            float corr = __expf(m_r[rr] - m_new);
            float p0 = __expf(s0 - m_new);
            float p1 = __expf(s1 - m_new);
            float p2 = __expf(s2 - m_new);
            float p3 = __expf(s3 - m_new);
            float ps = (p0 + p1) + (p2 + p3);
#pragma unroll
            for (int o = 16; o > 0; o >>= 1)
                ps += __shfl_xor_sync(0xffffffffu, ps, o);
            l_r[rr] = l_r[rr] * corr + ps;
            m_r[rr] = m_new;
            sS[row*FQKP + lane]      = tf32_round(p0);
            sS[row*FQKP + 32 + lane] = tf32_round(p1);
            sS[row*FQKP + 64 + lane] = tf32_round(p2);
            sS[row*FQKP + 96 + lane] = tf32_round(p3);
            if (lane == 0) scorr[row] = corr;
        }
        __syncthreads();

        // ---- PV: warp tile 64x32 at (wm*64, wn*32), 16 ks steps ----
        float cr0[4], cr1[4];
#pragma unroll
        for (int i = 0; i < 4; i++) {
            const int row = wm*64 + i*16 + qd;
            cr0[i] = scorr[row];
            cr1[i] = scorr[row+8];
        }
#pragma unroll
        for (int i = 0; i < 4; i++)
#pragma unroll
            for (int j = 0; j < 4; j++) {
                oacc[i][j][0] *= cr0[i]; oacc[i][j][1] *= cr0[i];
                oacc[i][j][2] *= cr1[i]; oacc[i][j][3] *= cr1[i];
            }

        const uint32_t aS0 = smb + (uint32_t)((FSS + (wm*64)*FQKP)*4) + lmQK;
        const uint32_t bV0 = smb + (uint32_t)((FSV + (wn*32)*FQKP)*4) + lmQK;
#pragma unroll
        for (int ks = 0; ks < 16; ks++) {
            const uint32_t kk4 = (uint32_t)(ks*32);
            uint32_t pa[4][4], vb[4][2];
#pragma unroll
            for (int i = 0; i < 4; i++)
                LDSM4(pa[i][0], pa[i][1], pa[i][2], pa[i][3],
                      aS0 + (uint32_t)(i*16*FQKP*4) + kk4);
            LDSM4(vb[0][0], vb[1][0], vb[0][1], vb[1][1], bV0 + kk4);
            LDSM4(vb[2][0], vb[3][0], vb[2][1], vb[3][1],
                  bV0 + (uint32_t)(16*FQKP*4) + kk4);
#pragma unroll
            for (int i = 0; i < 4; i++)
#pragma unroll
                for (int j = 0; j < 4; j++)
                    mma_tf32(oacc[i][j], pa[i], vb[j]);
        }
    }

    __syncthreads();
#pragma unroll
    for (int rr = 0; rr < 16; rr++)
        if (lane == 0) scorr[warp*16 + rr] = 1.f / l_r[rr];
    __syncthreads();

    // epilogue (tf32-rounded for the tf32 O-projection)
#pragma unroll
    for (int i = 0; i < 4; i++) {
        const int row = wm*64 + i*16 + qd;
        const float inv0 = scorr[row], inv1 = scorr[row+8];
        float* d0 = ctx + ((size_t)(b*SEQ + grow0 + row  ) * NH + h) * HD;
        float* d1 = ctx + ((size_t)(b*SEQ + grow0 + row+8) * NH + h) * HD;
#pragma unroll
        for (int j = 0; j < 4; j++) {
            const int col = wn*32 + j*8 + 2*r4;
            float2 lo, hi;
            lo.x = tf32_round(oacc[i][j][0]*inv0);
            lo.y = tf32_round(oacc[i][j][1]*inv0);
            hi.x = tf32_round(oacc[i][j][2]*inv1);
            hi.y = tf32_round(oacc[i][j][3]*inv1);
            *(float2*)(d0 + col) = lo;
            *(float2*)(d1 + col) = hi;
        }
    }
}

// ---------------------------------------------------------------------------
extern "C" void kernel_launch(void* const* d_in, const int* in_sizes, int n_in,
                              void* d_out, int out_size)
{
    const float* hs   = (const float*)d_in[0];
    const float* cosp = (const float*)d_in[1];
    const float* sinp = (const float*)d_in[2];
    const float* Wq   = (const float*)d_in[3];
    const float* Wk   = (const float*)d_in[4];
    const float* Wv   = (const float*)d_in[5];
    const float* Wo   = (const float*)d_in[6];
    float* out = (float*)d_out;

    float *qkv, *ctx, *hs_t, *wqkv, *wo;
    cudaGetSymbolAddress((void**)&qkv,  g_qkv);
    cudaGetSymbolAddress((void**)&ctx,  g_ctx);
    cudaGetSymbolAddress((void**)&hs_t, g_hs);
    cudaGetSymbolAddress((void**)&wqkv, g_wqkv);
    cudaGetSymbolAddress((void**)&wo,   g_wo);

    cudaFuncSetAttribute(gemm_mma, cudaFuncAttributeMaxDynamicSharedMemorySize,
                         (int)GEMM_SMEM);
    cudaFuncSetAttribute(flash_mma_kernel, cudaFuncAttributeMaxDynamicSharedMemorySize,
                         (int)FLASH_SMEM);

    const int M = MTOT;  // 4096

    // 1) fused tf32 pre-rounding of all inputs
    round5_kernel<<<(N4_TOT + 255)/256, 256>>>(hs, Wq, Wk, Wv, Wo,
                                               hs_t, wqkv, wo);

    // 2) fused QKV projection (CTA 128x256, 512 threads)
    gemm_mma<<<dim3(QKVW/256, M/128), 512, GEMM_SMEM>>>(hs_t, wqkv, qkv,
                                                        M, QKVW, HIDDEN);

    // 3) fused RoPE + rounding of q/k/v
    rope_round_kernel<<<(ROPE_TOT + 255)/256, 256>>>(qkv, cosp, sinp);

    // 4) attention (Br=Bc=128, 256 threads, 64x32 warp tiles)
    flash_mma_kernel<<<dim3(SEQ/128, NH, BATCH), 256, FLASH_SMEM>>>(qkv, ctx);

    // 5) output projection
    gemm_mma<<<dim3(HIDDEN/256, M/128), 512, GEMM_SMEM>>>(ctx, wo, out,
                                                          M, HIDDEN, HIDDEN);
}

// round 12
// speedup vs baseline: 1.0489x; 1.0489x over previous
#include <cuda_runtime.h>
#include <math.h>
#include <stdint.h>

#define BATCH 2
#define SEQ 2048
#define HIDDEN 2048
#define NH 16
#define KVH 4
#define HD 128
#define MTOT (BATCH*SEQ)
#define QKVW 3072
#define KOFF 2048
#define VOFF 2560

// scratch (no allocation allowed -> device globals)
__device__ float g_qkv[MTOT*QKVW];
__device__ float g_ctx[MTOT*HIDDEN];
__device__ float g_hs[MTOT*HIDDEN];
__device__ float g_wqkv[QKVW*HIDDEN];
__device__ float g_wo[HIDDEN*HIDDEN];

// ===========================================================================
// helpers
// ===========================================================================
__device__ __forceinline__ uint32_t smem_u32(const void* p) {
    uint32_t a;
    asm("{ .reg .u64 t; cvta.to.shared.u64 t, %1; cvt.u32.u64 %0, t; }"
        : "=r"(a) : "l"(p));
    return a;
}
__device__ __forceinline__ void cp_async16(uint32_t saddr, const void* gaddr) {
    asm volatile("cp.async.cg.shared.global [%0], [%1], 16;"
                 :: "r"(saddr), "l"(gaddr));
}
__device__ __forceinline__ void cp_commit() {
    asm volatile("cp.async.commit_group;" ::: "memory");
}
__device__ __forceinline__ void cp_wait2() {
    asm volatile("cp.async.wait_group 2;" ::: "memory");
}
__device__ __forceinline__ void cp_wait0() {
    asm volatile("cp.async.wait_group 0;" ::: "memory");
}
__device__ __forceinline__ float tf32_round(float x) {
    uint32_t u;
    asm("cvt.rna.tf32.f32 %0, %1;" : "=r"(u) : "f"(x));
    return __uint_as_float(u);
}
__device__ __forceinline__ void mma_tf32(float* d, const uint32_t* a, const uint32_t* b) {
    asm volatile(
        "mma.sync.aligned.m16n8k8.row.col.f32.tf32.tf32.f32 "
        "{%0,%1,%2,%3}, {%4,%5,%6,%7}, {%8,%9}, {%0,%1,%2,%3};"
        : "+f"(d[0]), "+f"(d[1]), "+f"(d[2]), "+f"(d[3])
        : "r"(a[0]), "r"(a[1]), "r"(a[2]), "r"(a[3]), "r"(b[0]), "r"(b[1]));
}
#define LDSM4(r0,r1,r2,r3,addr)                                              \
    asm volatile("ldmatrix.sync.aligned.m8n8.x4.shared.b16 {%0,%1,%2,%3}, [%4];" \
        : "=r"(r0), "=r"(r1), "=r"(r2), "=r"(r3) : "r"(addr))

// ===========================================================================
// fused tf32 rounding pass: hs -> g_hs, [Wq|Wk|Wv] -> g_wqkv, Wo -> g_wo
// ===========================================================================
#define N4_HS  (MTOT*HIDDEN/4)
#define N4_WQ  (HIDDEN*HIDDEN/4)
#define N4_WKV (KVH*HD*HIDDEN/4)
#define N4_TOT (N4_HS + 2*N4_WQ + 2*N4_WKV)

__global__ void round5_kernel(
    const float* __restrict__ hs, const float* __restrict__ wq,
    const float* __restrict__ wk, const float* __restrict__ wv,
    const float* __restrict__ wo,
    float* __restrict__ dhs, float* __restrict__ dwqkv,
    float* __restrict__ dwo)
{
    int i = blockIdx.x * 256 + threadIdx.x;
    if (i >= N4_TOT) return;
    const float* src; float* dst; int j = i;
    if (j < N4_HS)                  { src = hs; dst = dhs; }
    else if ((j -= N4_HS) < N4_WQ)  { src = wq; dst = dwqkv; }
    else if ((j -= N4_WQ) < N4_WKV) { src = wk; dst = dwqkv + (size_t)KOFF*HIDDEN; }
    else if ((j -= N4_WKV) < N4_WKV){ src = wv; dst = dwqkv + (size_t)VOFF*HIDDEN; }
    else { j -= N4_WKV; src = wo; dst = dwo; }
    float4 v = ((const float4*)src)[j];
    v.x = tf32_round(v.x); v.y = tf32_round(v.y);
    v.z = tf32_round(v.z); v.w = tf32_round(v.w);
    ((float4*)dst)[j] = v;
}

// ===========================================================================
// tf32 mma.sync GEMM with ldmatrix. CTA 128x256, BK=32, 4-stage cp.async,
// 512 threads (16 warps, 2x8 grid, warp tile 64x32). N multiple of 256,
// K multiple of 128 (KT % 4 == 0).
// ===========================================================================
#define BK 32
#define APAD 36
#define STAGE_FLOATS ((128+256)*APAD)
#define NSTAGE 4
#define GEMM_SMEM (NSTAGE*STAGE_FLOATS*4)

__global__ void __launch_bounds__(512, 1) gemm_mma(
    const float* __restrict__ A, const float* __restrict__ B,
    float* __restrict__ C, int M, int N, int K)
{
    extern __shared__ float sm[];
    const uint32_t smb = smem_u32(sm);

    const int tid  = threadIdx.x;
    const int warp = tid >> 5, lane = tid & 31;
    const int wm = warp >> 3, wn = warp & 7;
    const int m0 = blockIdx.y << 7, n0 = blockIdx.x << 8;
    const int q = lane >> 2, r = lane & 3;

    const int lmt = lane >> 3, lmr = lane & 7;
    const uint32_t lmoff = (uint32_t)((((lmt & 1) << 3 | lmr) * APAD + ((lmt >> 1) << 2)) * 4);

    float acc[4][4][4];
#pragma unroll
    for (int i = 0; i < 4; i++)
#pragma unroll
        for (int j = 0; j < 4; j++)
            acc[i][j][0]=acc[i][j][1]=acc[i][j][2]=acc[i][j][3]=0.f;

    const int arow0 = tid >> 3, ach = (tid & 7) << 2;

#define LOAD_TILE(s, kt) do {                                               \
    const uint32_t sA_ = smb + (uint32_t)(s)*STAGE_FLOATS*4;                \
    const uint32_t sB_ = sA_ + 128*APAD*4;                                  \
    const int koff = (kt) * BK;                                             \
    _Pragma("unroll")                                                       \
    for (int l_ = 0; l_ < 2; l_++) {                                        \
        int row = arow0 + l_*64;                                            \
        cp_async16(sA_ + (uint32_t)(row*APAD + ach)*4,                      \
                   A + (size_t)(m0 + row) * K + koff + ach);                \
    }                                                                       \
    _Pragma("unroll")                                                       \
    for (int l_ = 0; l_ < 4; l_++) {                                        \
        int row = arow0 + l_*64;                                            \
        cp_async16(sB_ + (uint32_t)(row*APAD + ach)*4,                      \
                   B + (size_t)(n0 + row) * K + koff + ach);                \
    } } while (0)

    const int KT = K / BK;
    LOAD_TILE(0, 0); cp_commit();
    LOAD_TILE(1, 1); cp_commit();
    LOAD_TILE(2, 2); cp_commit();
    cp_wait2();
    __syncthreads();

    for (int kt = 0; kt < KT; kt++) {
        const int nxt = kt + 3;
        if (nxt < KT) {
            LOAD_TILE(nxt & 3, nxt);
        }
        cp_commit();

        const int cs = kt & 3;
        const uint32_t sAb = smb + (uint32_t)cs*STAGE_FLOATS*4;
        const uint32_t sBb = sAb + 128*APAD*4;

#pragma unroll
        for (int ks = 0; ks < 4; ks++) {
            const int kk = ks * 8;
            uint32_t afr[4][4], bfr[4][2];
#pragma unroll
            for (int i = 0; i < 4; i++)
                LDSM4(afr[i][0], afr[i][1], afr[i][2], afr[i][3],
                      sAb + (uint32_t)(((wm*64 + i*16)*APAD + kk)*4) + lmoff);
            LDSM4(bfr[0][0], bfr[1][0], bfr[0][1], bfr[1][1],
                  sBb + (uint32_t)(((wn*32)*APAD + kk)*4) + lmoff);
            LDSM4(bfr[2][0], bfr[3][0], bfr[2][1], bfr[3][1],
                  sBb + (uint32_t)(((wn*32 + 16)*APAD + kk)*4) + lmoff);
#pragma unroll
            for (int i = 0; i < 4; i++)
#pragma unroll
                for (int j = 0; j < 4; j++)
                    mma_tf32(acc[i][j], afr[i], bfr[j]);
        }

        cp_wait2();
        __syncthreads();
    }

#pragma unroll
    for (int i = 0; i < 4; i++) {
        const int row = m0 + wm*64 + i*16 + q;
#pragma unroll
        for (int j = 0; j < 4; j++) {
            const int col = n0 + wn*32 + j*8 + 2*r;
            float2 lo; lo.x = acc[i][j][0]; lo.y = acc[i][j][1];
            float2 hi; hi.x = acc[i][j][2]; hi.y = acc[i][j][3];
            *(float2*)(C + (size_t)row * N + col)       = lo;
            *(float2*)(C + (size_t)(row+8) * N + col)   = hi;
        }
    }
#undef LOAD_TILE
}

// ---------------------------------------------------------------------------
// fused RoPE + tf32 rounding: q (rope+round), k (rope+round), v (round only)
// ---------------------------------------------------------------------------
#define ROPE_NQ (MTOT*NH*64)
#define ROPE_NK (MTOT*KVH*64)
#define ROPE_NV (MTOT*128)
#define ROPE_TOT (ROPE_NQ + ROPE_NK + ROPE_NV)

__global__ void rope_round_kernel(float* __restrict__ qkv,
                                  const float* __restrict__ cs,
                                  const float* __restrict__ sn)
{
    int idx = blockIdx.x * 256 + threadIdx.x;
    if (idx < ROPE_NQ) {
        int d = idx & 63;
        int h = (idx >> 6) % NH;
        int t = idx / (NH << 6);
        float* row = qkv + (size_t)t * QKVW + h * HD;
        int s = t & (SEQ - 1);
        float x1 = row[d], x2 = row[d + 64];
        row[d]      = tf32_round(x1 * cs[s*HD + d]      - x2 * sn[s*HD + d]);
        row[d + 64] = tf32_round(x2 * cs[s*HD + d + 64] + x1 * sn[s*HD + d + 64]);
    } else if ((idx -= ROPE_NQ) < ROPE_NK) {
        int d = idx & 63;
        int h = (idx >> 6) % KVH;
        int t = idx / (KVH << 6);
        float* row = qkv + (size_t)t * QKVW + KOFF + h * HD;
        int s = t & (SEQ - 1);
        float x1 = row[d], x2 = row[d + 64];
        row[d]      = tf32_round(x1 * cs[s*HD + d]      - x2 * sn[s*HD + d]);
        row[d + 64] = tf32_round(x2 * cs[s*HD + d + 64] + x1 * sn[s*HD + d + 64]);
    } else if ((idx -= ROPE_NK) < ROPE_NV) {
        int t = idx >> 7, c4 = (idx & 127) << 2;
        float* p = qkv + (size_t)t * QKVW + VOFF + c4;
        float4 v = *(float4*)p;
        v.x = tf32_round(v.x); v.y = tf32_round(v.y);
        v.z = tf32_round(v.z); v.w = tf32_round(v.w);
        *(float4*)p = v;
    }
}

// ---------------------------------------------------------------------------
// Flash attention, mma.sync tf32 + ldmatrix. Br=128, Bc=128, D=128.
// 512 threads (16 warps, 4x4 grid, warp tile 32x32 in QK and PV -> 2.0 wf/MMA
// with 4 warps/SMSP). sS overlaid on sK.
// ---------------------------------------------------------------------------
#define FQKP 132
#define FSQ 0
#define FSK (128*FQKP)
#define FSV (FSK + 128*FQKP)
#define FSS FSK                      // overlay: scores reuse the K region
#define FSC (FSV + 128*FQKP)
#define FLASH_FLOATS (FSC + 128)
#define FLASH_SMEM (FLASH_FLOATS*4)

__global__ void __launch_bounds__(512, 1) flash_mma_kernel(
    const float* __restrict__ qkv, float* __restrict__ ctx)
{
    extern __shared__ float sm[];
    const uint32_t smb = smem_u32(sm);
    float* sS   = sm + FSS;
    float* scorr= sm + FSC;

    const int b = blockIdx.z, h = blockIdx.y;
    const int qb = (int)gridDim.x - 1 - (int)blockIdx.x;   // long CTAs first
    const int kh = h >> 2;
    const int tid = threadIdx.x;
    const int warp = tid >> 5, lane = tid & 31;
    const int wm = warp >> 2, wn = warp & 3;               // 4 x 4 warp grid
    const int qd = lane >> 2, r4 = lane & 3;

    const int lmt = lane >> 3, lmr = lane & 7;
    const int lmrow = ((lmt & 1) << 3) | lmr;
    const int lmcol = (lmt >> 1) << 2;
    const uint32_t lmQK = (uint32_t)((lmrow*FQKP + lmcol) * 4);

    // ---- Q tile via cp.async (128 x 128) ----
    const float* qbase = qkv + (size_t)(b*SEQ + qb*128) * QKVW + h * HD;
#pragma unroll
    for (int l = 0; l < 8; l++) {
        int idx = tid + l*512;
        int row = idx >> 5, c4 = (idx & 31) << 2;
        cp_async16(smb + (uint32_t)((FSQ + row*FQKP + c4)*4),
                   qbase + (size_t)row * QKVW + c4);
    }
    cp_commit();

    float m_r[8], l_r[8];
#pragma unroll
    for (int i = 0; i < 8; i++) { m_r[i] = -1e30f; l_r[i] = 0.f; }

    float oacc[2][4][4];
#pragma unroll
    for (int i = 0; i < 2; i++)
#pragma unroll
        for (int j = 0; j < 4; j++)
            oacc[i][j][0]=oacc[i][j][1]=oacc[i][j][2]=oacc[i][j][3]=0.f;

    const int grow0 = qb * 128;
    const float sscale = 0.08838834764831845f;

    // V transpose mapping: 2 iters x (4x4 block per thread)
    for (int jb = 0; jb <= qb; jb++) {
        __syncthreads();   // prior PV done with sS/sVt
        const float* kbase = qkv + (size_t)(b*SEQ + jb*128) * QKVW + KOFF + kh * HD;
        const float* vbase = qkv + (size_t)(b*SEQ + jb*128) * QKVW + VOFF + kh * HD;
        // K via cp.async (128 x 128) into sK (== sS region)
#pragma unroll
        for (int l = 0; l < 8; l++) {
            int idx = tid + l*512;
            int row = idx >> 5, c4 = (idx & 31) << 2;
            cp_async16(smb + (uint32_t)((FSK + row*FQKP + c4)*4),
                       kbase + (size_t)row * QKVW + c4);
        }
        cp_commit();
        // V transposed into sVt [d:128][j:128] stride 132 (conflict-free STS.128)
#pragma unroll
        for (int l = 0; l < 2; l++) {
            const int id = tid + l*512;
            const int j0 = (id & 31) << 2;
            const int d0 = (id >> 5) << 2;
            float4 v0 = *(const float4*)(vbase + (size_t)(j0+0) * QKVW + d0);
            float4 v1 = *(const float4*)(vbase + (size_t)(j0+1) * QKVW + d0);
            float4 v2 = *(const float4*)(vbase + (size_t)(j0+2) * QKVW + d0);
            float4 v3 = *(const float4*)(vbase + (size_t)(j0+3) * QKVW + d0);
            float4 t;
            t.x=v0.x; t.y=v1.x; t.z=v2.x; t.w=v3.x;
            *(float4*)&sm[FSV + (d0+0)*FQKP + j0] = t;
            t.x=v0.y; t.y=v1.y; t.z=v2.y; t.w=v3.y;
            *(float4*)&sm[FSV + (d0+1)*FQKP + j0] = t;
            t.x=v0.z; t.y=v1.z; t.z=v2.z; t.w=v3.z;
            *(float4*)&sm[FSV + (d0+2)*FQKP + j0] = t;
            t.x=v0.w; t.y=v1.w; t.z=v2.w; t.w=v3.w;
            *(float4*)&sm[FSV + (d0+3)*FQKP + j0] = t;
        }
        cp_wait0();
        __syncthreads();

        // ---- QK: warp tile 32x32 at (wm*32, wn*32), 16 ks steps ----
        float sc[2][4][4];
#pragma unroll
        for (int i = 0; i < 2; i++)
#pragma unroll
            for (int j = 0; j < 4; j++)
                sc[i][j][0]=sc[i][j][1]=sc[i][j][2]=sc[i][j][3]=0.f;

        const uint32_t aQ0 = smb + (uint32_t)((FSQ + (wm*32)*FQKP)*4) + lmQK;
        const uint32_t bK0 = smb + (uint32_t)((FSK + (wn*32)*FQKP)*4) + lmQK;
#pragma unroll
        for (int ks = 0; ks < 16; ks++) {
            const uint32_t kk4 = (uint32_t)(ks*32);
            uint32_t qa[2][4], kb[4][2];
            LDSM4(qa[0][0], qa[0][1], qa[0][2], qa[0][3], aQ0 + kk4);
            LDSM4(qa[1][0], qa[1][1], qa[1][2], qa[1][3],
                  aQ0 + (uint32_t)(16*FQKP*4) + kk4);
            LDSM4(kb[0][0], kb[1][0], kb[0][1], kb[1][1], bK0 + kk4);
            LDSM4(kb[2][0], kb[3][0], kb[2][1], kb[3][1],
                  bK0 + (uint32_t)(16*FQKP*4) + kk4);
#pragma unroll
            for (int i = 0; i < 2; i++)
#pragma unroll
                for (int j = 0; j < 4; j++)
                    mma_tf32(sc[i][j], qa[i], kb[j]);
        }
        __syncthreads();   // all K reads done before sS overlays the region

        // store scaled scores to sS (overlaid on sK)
#pragma unroll
        for (int i = 0; i < 2; i++) {
            const int row = wm*32 + i*16 + qd;
#pragma unroll
            for (int j = 0; j < 4; j++) {
                const int col = wn*32 + j*8 + 2*r4;
                float2 lo; lo.x = sc[i][j][0]*sscale; lo.y = sc[i][j][1]*sscale;
                float2 hi; hi.x = sc[i][j][2]*sscale; hi.y = sc[i][j][3]*sscale;
                *(float2*)&sS[row*FQKP + col]     = lo;
                *(float2*)&sS[(row+8)*FQKP + col] = hi;
            }
        }
        __syncthreads();

        // ---- softmax (scalar fp32), warp owns rows warp*8..+7 ----
        const bool diag = (jb == qb);
        const int col0 = jb * 128;
#pragma unroll
        for (int rr = 0; rr < 8; rr++) {
            int row = warp*8 + rr;
            int grow = grow0 + row;
            float s0 = sS[row*FQKP + lane];
            float s1 = sS[row*FQKP + 32 + lane];
            float s2 = sS[row*FQKP + 64 + lane];
            float s3 = sS[row*FQKP + 96 + lane];
            if (diag) {
                if (col0 + lane > grow)      s0 = -1e30f;
                if (col0 + 32 + lane > grow) s1 = -1e30f;
                if (col0 + 64 + lane > grow) s2 = -1e30f;
                if (col0 + 96 + lane > grow) s3 = -1e30f;
            }
            float mx = fmaxf(fmaxf(s0, s1), fmaxf(s2, s3));
#pragma unroll
            for (int o = 16; o > 0; o >>= 1)
                mx = fmaxf(mx, __shfl_xor_sync(0xffffffffu, mx, o));
            float m_new = fmaxf(m_r[rr], mx);
            float corr = __expf(m_r[rr] - m_new);
            float p0 = __expf(s0 - m_new);
            float p1 = __expf(s1 - m_new);
            float p2 = __expf(s2 - m_new);
            float p3 = __expf(s3 - m_new);
            float ps = (p0 + p1) + (p2 + p3);
#pragma unroll
            for (int o = 16; o > 0; o >>= 1)
                ps += __shfl_xor_sync(0xffffffffu, ps, o);
            l_r[rr] = l_r[rr] * corr + ps;
            m_r[rr] = m_new;
            sS[row*FQKP + lane]      = tf32_round(p0);
            sS[row*FQKP + 32 + lane] = tf32_round(p1);
            sS[row*FQKP + 64 + lane] = tf32_round(p2);
            sS[row*FQKP + 96 + lane] = tf32_round(p3);
            if (lane == 0) scorr[row] = corr;
        }
        __syncthreads();

        // ---- PV: warp tile 32x32 at (wm*32, wn*32), 16 ks steps ----
        float cr0[2], cr1[2];
#pragma unroll
        for (int i = 0; i < 2; i++) {
            const int row = wm*32 + i*16 + qd;
            cr0[i] = scorr[row];
            cr1[i] = scorr[row+8];
        }
#pragma unroll
        for (int i = 0; i < 2; i++)
#pragma unroll
            for (int j = 0; j < 4; j++) {
                oacc[i][j][0] *= cr0[i]; oacc[i][j][1] *= cr0[i];
                oacc[i][j][2] *= cr1[i]; oacc[i][j][3] *= cr1[i];
            }

        const uint32_t aS0 = smb + (uint32_t)((FSS + (wm*32)*FQKP)*4) + lmQK;
        const uint32_t bV0 = smb + (uint32_t)((FSV + (wn*32)*FQKP)*4) + lmQK;
#pragma unroll
        for (int ks = 0; ks < 16; ks++) {
            const uint32_t kk4 = (uint32_t)(ks*32);
            uint32_t pa[2][4], vb[4][2];
            LDSM4(pa[0][0], pa[0][1], pa[0][2], pa[0][3], aS0 + kk4);
            LDSM4(pa[1][0], pa[1][1], pa[1][2], pa[1][3],
                  aS0 + (uint32_t)(16*FQKP*4) + kk4);
            LDSM4(vb[0][0], vb[1][0], vb[0][1], vb[1][1], bV0 + kk4);
            LDSM4(vb[2][0], vb[3][0], vb[2][1], vb[3][1],
                  bV0 + (uint32_t)(16*FQKP*4) + kk4);
#pragma unroll
            for (int i = 0; i < 2; i++)
#pragma unroll
                for (int j = 0; j < 4; j++)
                    mma_tf32(oacc[i][j], pa[i], vb[j]);
        }
    }

    __syncthreads();
#pragma unroll
    for (int rr = 0; rr < 8; rr++)
        if (lane == 0) scorr[warp*8 + rr] = 1.f / l_r[rr];
    __syncthreads();

    // epilogue (tf32-rounded for the tf32 O-projection)
#pragma unroll
    for (int i = 0; i < 2; i++) {
        const int row = wm*32 + i*16 + qd;
        const float inv0 = scorr[row], inv1 = scorr[row+8];
        float* d0 = ctx + ((size_t)(b*SEQ + grow0 + row  ) * NH + h) * HD;
        float* d1 = ctx + ((size_t)(b*SEQ + grow0 + row+8) * NH + h) * HD;
#pragma unroll
        for (int j = 0; j < 4; j++) {
            const int col = wn*32 + j*8 + 2*r4;
            float2 lo, hi;
            lo.x = tf32_round(oacc[i][j][0]*inv0);
            lo.y = tf32_round(oacc[i][j][1]*inv0);
            hi.x = tf32_round(oacc[i][j][2]*inv1);
            hi.y = tf32_round(oacc[i][j][3]*inv1);
            *(float2*)(d0 + col) = lo;
            *(float2*)(d1 + col) = hi;
        }
    }
}

// ---------------------------------------------------------------------------
extern "C" void kernel_launch(void* const* d_in, const int* in_sizes, int n_in,
                              void* d_out, int out_size)
{
    const float* hs   = (const float*)d_in[0];
    const float* cosp = (const float*)d_in[1];
    const float* sinp = (const float*)d_in[2];
    const float* Wq   = (const float*)d_in[3];
    const float* Wk   = (const float*)d_in[4];
    const float* Wv   = (const float*)d_in[5];
    const float* Wo   = (const float*)d_in[6];
    float* out = (float*)d_out;

    float *qkv, *ctx, *hs_t, *wqkv, *wo;
    cudaGetSymbolAddress((void**)&qkv,  g_qkv);
    cudaGetSymbolAddress((void**)&ctx,  g_ctx);
    cudaGetSymbolAddress((void**)&hs_t, g_hs);
    cudaGetSymbolAddress((void**)&wqkv, g_wqkv);
    cudaGetSymbolAddress((void**)&wo,   g_wo);

    cudaFuncSetAttribute(gemm_mma, cudaFuncAttributeMaxDynamicSharedMemorySize,
                         (int)GEMM_SMEM);
    cudaFuncSetAttribute(flash_mma_kernel, cudaFuncAttributeMaxDynamicSharedMemorySize,
                         (int)FLASH_SMEM);

    const int M = MTOT;  // 4096

    // 1) fused tf32 pre-rounding of all inputs
    round5_kernel<<<(N4_TOT + 255)/256, 256>>>(hs, Wq, Wk, Wv, Wo,
                                               hs_t, wqkv, wo);

    // 2) fused QKV projection (CTA 128x256, 512 threads, 4 stages)
    gemm_mma<<<dim3(QKVW/256, M/128), 512, GEMM_SMEM>>>(hs_t, wqkv, qkv,
                                                        M, QKVW, HIDDEN);

    // 3) fused RoPE + rounding of q/k/v
    rope_round_kernel<<<(ROPE_TOT + 255)/256, 256>>>(qkv, cosp, sinp);

    // 4) attention (Br=Bc=128, 512 threads, 32x32 warp tiles)
    flash_mma_kernel<<<dim3(SEQ/128, NH, BATCH), 512, FLASH_SMEM>>>(qkv, ctx);

    // 5) output projection
    gemm_mma<<<dim3(HIDDEN/256, M/128), 512, GEMM_SMEM>>>(ctx, wo, out,
                                                          M, HIDDEN, HIDDEN);
}

// round 13
// speedup vs baseline: 1.4142x; 1.3483x over previous
#include <cuda_runtime.h>
#include <cuda_fp16.h>
#include <math.h>
#include <stdint.h>

#define BATCH 2
#define SEQ 2048
#define HIDDEN 2048
#define NH 16
#define KVH 4
#define HD 128
#define MTOT (BATCH*SEQ)
#define QKVW 3072
#define KOFF 2048
#define VOFF 2560
#define SSCALE 0.08838834764831845f

// scratch (no allocation allowed -> device globals), all fp16
__device__ __align__(16) __half g_qkv[MTOT*QKVW];
__device__ __align__(16) __half g_ctx[MTOT*HIDDEN];
__device__ __align__(16) __half g_hs[MTOT*HIDDEN];
__device__ __align__(16) __half g_wqkv[QKVW*HIDDEN];
__device__ __align__(16) __half g_wo[HIDDEN*HIDDEN];

// ===========================================================================
// helpers
// ===========================================================================
__device__ __forceinline__ uint32_t smem_u32(const void* p) {
    uint32_t a;
    asm("{ .reg .u64 t; cvta.to.shared.u64 t, %1; cvt.u32.u64 %0, t; }"
        : "=r"(a) : "l"(p));
    return a;
}
__device__ __forceinline__ void cp_async16(uint32_t saddr, const void* gaddr) {
    asm volatile("cp.async.cg.shared.global [%0], [%1], 16;"
                 :: "r"(saddr), "l"(gaddr));
}
__device__ __forceinline__ void cp_commit() {
    asm volatile("cp.async.commit_group;" ::: "memory");
}
__device__ __forceinline__ void cp_wait2() {
    asm volatile("cp.async.wait_group 2;" ::: "memory");
}
__device__ __forceinline__ void cp_wait0() {
    asm volatile("cp.async.wait_group 0;" ::: "memory");
}
// D += A*B : fp16 m16n8k16, fp32 accumulate
__device__ __forceinline__ void mma_f16(float* d, const uint32_t* a, const uint32_t* b) {
    asm volatile(
        "mma.sync.aligned.m16n8k16.row.col.f32.f16.f16.f32 "
        "{%0,%1,%2,%3}, {%4,%5,%6,%7}, {%8,%9}, {%0,%1,%2,%3};"
        : "+f"(d[0]), "+f"(d[1]), "+f"(d[2]), "+f"(d[3])
        : "r"(a[0]), "r"(a[1]), "r"(a[2]), "r"(a[3]), "r"(b[0]), "r"(b[1]));
}
#define LDSM4(r0,r1,r2,r3,addr)                                              \
    asm volatile("ldmatrix.sync.aligned.m8n8.x4.shared.b16 {%0,%1,%2,%3}, [%4];" \
        : "=r"(r0), "=r"(r1), "=r"(r2), "=r"(r3) : "r"(addr))

// ===========================================================================
// fused fp16 conversion pass: hs -> g_hs, [Wq|Wk|Wv] -> g_wqkv, Wo -> g_wo
// ===========================================================================
#define N4_HS  (MTOT*HIDDEN/4)
#define N4_WQ  (HIDDEN*HIDDEN/4)
#define N4_WKV (KVH*HD*HIDDEN/4)
#define N4_TOT (N4_HS + 2*N4_WQ + 2*N4_WKV)

__global__ void round5_kernel(
    const float* __restrict__ hs, const float* __restrict__ wq,
    const float* __restrict__ wk, const float* __restrict__ wv,
    const float* __restrict__ wo,
    __half* __restrict__ dhs, __half* __restrict__ dwqkv,
    __half* __restrict__ dwo)
{
    int i = blockIdx.x * 256 + threadIdx.x;
    if (i >= N4_TOT) return;
    const float* src; __half* dst; int j = i;
    if (j < N4_HS)                  { src = hs; dst = dhs; }
    else if ((j -= N4_HS) < N4_WQ)  { src = wq; dst = dwqkv; }
    else if ((j -= N4_WQ) < N4_WKV) { src = wk; dst = dwqkv + (size_t)KOFF*HIDDEN; }
    else if ((j -= N4_WKV) < N4_WKV){ src = wv; dst = dwqkv + (size_t)VOFF*HIDDEN; }
    else { j -= N4_WKV; src = wo; dst = dwo; }
    float4 v = ((const float4*)src)[j];
    __half2 a = __floats2half2_rn(v.x, v.y);
    __half2 b = __floats2half2_rn(v.z, v.w);
    ((__half2*)dst)[2*j]   = a;
    ((__half2*)dst)[2*j+1] = b;
}

// ===========================================================================
// fp16 mma.sync GEMM with ldmatrix. CTA 128x256, BK=64 halves, 4-stage
// cp.async, 512 threads (16 warps, 2x8 grid, warp tile 64x32).
// N multiple of 256, K multiple of 256. Output fp16 or fp32 per flag.
// ===========================================================================
#define BKH 64
#define APADH 72                         // halves per row (144B)
#define STAGE_HALVES ((128+256)*APADH)
#define NSTAGE 4
#define GEMM_SMEM (NSTAGE*STAGE_HALVES*2)

__global__ void __launch_bounds__(512, 1) gemm_mma(
    const __half* __restrict__ A, const __half* __restrict__ B,
    void* __restrict__ Cv, int M, int N, int K, int store_half)
{
    extern __shared__ __half smh[];
    const uint32_t smb = smem_u32(smh);

    const int tid  = threadIdx.x;
    const int warp = tid >> 5, lane = tid & 31;
    const int wm = warp >> 3, wn = warp & 7;
    const int m0 = blockIdx.y << 7, n0 = blockIdx.x << 8;
    const int q = lane >> 2, r = lane & 3;

    const int lmt = lane >> 3, lmr = lane & 7;
    const uint32_t lmoff = (uint32_t)((((lmt & 1) << 3 | lmr) * APADH + ((lmt >> 1) << 3)) * 2);

    float acc[4][4][4];
#pragma unroll
    for (int i = 0; i < 4; i++)
#pragma unroll
        for (int j = 0; j < 4; j++)
            acc[i][j][0]=acc[i][j][1]=acc[i][j][2]=acc[i][j][3]=0.f;

    const int arow0 = tid >> 3, ach = (tid & 7) << 3;   // 8 halves (16B) chunks

#define LOAD_TILE(s, kt) do {                                               \
    const uint32_t sA_ = smb + (uint32_t)(s)*STAGE_HALVES*2;                \
    const uint32_t sB_ = sA_ + 128*APADH*2;                                 \
    const int koff = (kt) * BKH;                                            \
    _Pragma("unroll")                                                       \
    for (int l_ = 0; l_ < 2; l_++) {                                        \
        int row = arow0 + l_*64;                                            \
        cp_async16(sA_ + (uint32_t)(row*APADH + ach)*2,                     \
                   A + (size_t)(m0 + row) * K + koff + ach);                \
    }                                                                       \
    _Pragma("unroll")                                                       \
    for (int l_ = 0; l_ < 4; l_++) {                                        \
        int row = arow0 + l_*64;                                            \
        cp_async16(sB_ + (uint32_t)(row*APADH + ach)*2,                     \
                   B + (size_t)(n0 + row) * K + koff + ach);                \
    } } while (0)

    const int KT = K / BKH;
    LOAD_TILE(0, 0); cp_commit();
    LOAD_TILE(1, 1); cp_commit();
    LOAD_TILE(2, 2); cp_commit();
    cp_wait2();
    __syncthreads();

    for (int kt = 0; kt < KT; kt++) {
        const int nxt = kt + 3;
        if (nxt < KT) {
            LOAD_TILE(nxt & 3, nxt);
        }
        cp_commit();

        const int cs = kt & 3;
        const uint32_t sAb = smb + (uint32_t)cs*STAGE_HALVES*2;
        const uint32_t sBb = sAb + 128*APADH*2;

#pragma unroll
        for (int ks = 0; ks < 4; ks++) {
            const uint32_t kk2 = (uint32_t)(ks*32);     // 16 halves
            uint32_t afr[4][4], bfr[4][2];
#pragma unroll
            for (int i = 0; i < 4; i++)
                LDSM4(afr[i][0], afr[i][1], afr[i][2], afr[i][3],
                      sAb + (uint32_t)((wm*64 + i*16)*APADH*2) + lmoff + kk2);
            LDSM4(bfr[0][0], bfr[1][0], bfr[0][1], bfr[1][1],
                  sBb + (uint32_t)((wn*32)*APADH*2) + lmoff + kk2);
            LDSM4(bfr[2][0], bfr[3][0], bfr[2][1], bfr[3][1],
                  sBb + (uint32_t)((wn*32 + 16)*APADH*2) + lmoff + kk2);
#pragma unroll
            for (int i = 0; i < 4; i++)
#pragma unroll
                for (int j = 0; j < 4; j++)
                    mma_f16(acc[i][j], afr[i], bfr[j]);
        }

        cp_wait2();
        __syncthreads();
    }

    if (store_half) {
        __half* C = (__half*)Cv;
#pragma unroll
        for (int i = 0; i < 4; i++) {
            const int row = m0 + wm*64 + i*16 + q;
#pragma unroll
            for (int j = 0; j < 4; j++) {
                const int col = n0 + wn*32 + j*8 + 2*r;
                *(__half2*)(C + (size_t)row * N + col) =
                    __floats2half2_rn(acc[i][j][0], acc[i][j][1]);
                *(__half2*)(C + (size_t)(row+8) * N + col) =
                    __floats2half2_rn(acc[i][j][2], acc[i][j][3]);
            }
        }
    } else {
        float* C = (float*)Cv;
#pragma unroll
        for (int i = 0; i < 4; i++) {
            const int row = m0 + wm*64 + i*16 + q;
#pragma unroll
            for (int j = 0; j < 4; j++) {
                const int col = n0 + wn*32 + j*8 + 2*r;
                float2 lo; lo.x = acc[i][j][0]; lo.y = acc[i][j][1];
                float2 hi; hi.x = acc[i][j][2]; hi.y = acc[i][j][3];
                *(float2*)(C + (size_t)row * N + col)     = lo;
                *(float2*)(C + (size_t)(row+8) * N + col) = hi;
            }
        }
    }
#undef LOAD_TILE
}

// ---------------------------------------------------------------------------
// fused RoPE on fp16 q (with sscale folded) and k, in-place
// ---------------------------------------------------------------------------
#define ROPE_NQ (MTOT*NH*64)
#define ROPE_NK (MTOT*KVH*64)
#define ROPE_TOT (ROPE_NQ + ROPE_NK)

__global__ void rope_kernel(__half* __restrict__ qkv,
                            const float* __restrict__ cs,
                            const float* __restrict__ sn)
{
    int idx = blockIdx.x * 256 + threadIdx.x;
    if (idx < ROPE_NQ) {
        int d = idx & 63;
        int h = (idx >> 6) % NH;
        int t = idx / (NH << 6);
        __half* row = qkv + (size_t)t * QKVW + h * HD;
        int s = t & (SEQ - 1);
        float x1 = __half2float(row[d]), x2 = __half2float(row[d + 64]);
        row[d]      = __float2half((x1 * cs[s*HD + d]      - x2 * sn[s*HD + d])      * SSCALE);
        row[d + 64] = __float2half((x2 * cs[s*HD + d + 64] + x1 * sn[s*HD + d + 64]) * SSCALE);
    } else if ((idx -= ROPE_NQ) < ROPE_NK) {
        int d = idx & 63;
        int h = (idx >> 6) % KVH;
        int t = idx / (KVH << 6);
        __half* row = qkv + (size_t)t * QKVW + KOFF + h * HD;
        int s = t & (SEQ - 1);
        float x1 = __half2float(row[d]), x2 = __half2float(row[d + 64]);
        row[d]      = __float2half(x1 * cs[s*HD + d]      - x2 * sn[s*HD + d]);
        row[d + 64] = __float2half(x2 * cs[s*HD + d + 64] + x1 * sn[s*HD + d + 64]);
    }
}

// ---------------------------------------------------------------------------
// Flash attention, fp16 mma + ldmatrix + register-resident softmax.
// Br=Bc=128, D=128, 512 threads (16 warps, 4x4 grid, 32x32 warp tiles).
// Q pre-scaled by 1/sqrt(128) in rope. P stored fp16 (== tf32 precision).
// ---------------------------------------------------------------------------
#define FH 136                            // halves per row (272B)
#define SQ_B 0
#define SK_B (128*FH*2)
#define SV_B (SK_B + 128*FH*2)
#define SP_B (SV_B + 128*FH*2)
#define SRED_B  (SP_B + 128*FH*2)         // 128x4 floats
#define SRED2_B (SRED_B + 2048)
#define FLASH_SMEM (SRED2_B + 2048)

__global__ void __launch_bounds__(512, 1) flash_mma_kernel(
    const __half* __restrict__ qkv, __half* __restrict__ ctx)
{
    extern __shared__ char smc[];
    const uint32_t smb = smem_u32(smc);
    float* sRed  = (float*)(smc + SRED_B);
    float* sRed2 = (float*)(smc + SRED2_B);
    __half* sP   = (__half*)(smc + SP_B);

    const int b = blockIdx.z, h = blockIdx.y;
    const int qb = (int)gridDim.x - 1 - (int)blockIdx.x;   // long CTAs first
    const int kh = h >> 2;
    const int tid = threadIdx.x;
    const int warp = tid >> 5, lane = tid & 31;
    const int wm = warp >> 2, wn = warp & 3;               // 4 x 4 warp grid
    const int qd = lane >> 2, r4 = lane & 3;

    const int lmt = lane >> 3, lmr = lane & 7;
    const uint32_t lmoff = (uint32_t)((((lmt & 1) << 3 | lmr) * FH + ((lmt >> 1) << 3)) * 2);

    // ---- Q tile via cp.async (128 rows x 128 halves) ----
    const __half* qbase = qkv + (size_t)(b*SEQ + qb*128) * QKVW + h * HD;
#pragma unroll
    for (int l = 0; l < 4; l++) {
        int idx = tid + l*512;
        int row = idx >> 4, ch = (idx & 15) << 3;
        cp_async16(smb + (uint32_t)(SQ_B + (row*FH + ch)*2),
                   qbase + (size_t)row * QKVW + ch);
    }
    cp_commit();

    float m_r[4], l_r[4];
#pragma unroll
    for (int i = 0; i < 4; i++) { m_r[i] = -1e30f; l_r[i] = 0.f; }

    float oacc[2][4][4];
#pragma unroll
    for (int i = 0; i < 2; i++)
#pragma unroll
        for (int j = 0; j < 4; j++)
            oacc[i][j][0]=oacc[i][j][1]=oacc[i][j][2]=oacc[i][j][3]=0.f;

    const int grow0 = qb * 128;
    const int vj0 = (tid & 31) << 2;       // 4 j-rows
    const int vd0 = (tid >> 5) << 3;       // 8 d-cols

    for (int jb = 0; jb <= qb; jb++) {
        __syncthreads();   // prior PV done with sP/sVt
        const __half* kbase = qkv + (size_t)(b*SEQ + jb*128) * QKVW + KOFF + kh * HD;
        const __half* vbase = qkv + (size_t)(b*SEQ + jb*128) * QKVW + VOFF + kh * HD;
        // K via cp.async
#pragma unroll
        for (int l = 0; l < 4; l++) {
            int idx = tid + l*512;
            int row = idx >> 4, ch = (idx & 15) << 3;
            cp_async16(smb + (uint32_t)(SK_B + (row*FH + ch)*2),
                       kbase + (size_t)row * QKVW + ch);
        }
        cp_commit();
        // V transposed into sVt [d][j] halves (uint2 = 4-half stores, conflict-free)
        {
            uint4 lv0 = *(const uint4*)(vbase + (size_t)(vj0+0) * QKVW + vd0);
            uint4 lv1 = *(const uint4*)(vbase + (size_t)(vj0+1) * QKVW + vd0);
            uint4 lv2 = *(const uint4*)(vbase + (size_t)(vj0+2) * QKVW + vd0);
            uint4 lv3 = *(const uint4*)(vbase + (size_t)(vj0+3) * QKVW + vd0);
            const __half* h0 = (const __half*)&lv0;
            const __half* h1 = (const __half*)&lv1;
            const __half* h2 = (const __half*)&lv2;
            const __half* h3 = (const __half*)&lv3;
#pragma unroll
            for (int dd = 0; dd < 8; dd++) {
                __half2 pa = __halves2half2(h0[dd], h1[dd]);
                __half2 pb = __halves2half2(h2[dd], h3[dd]);
                uint2 st;
                st.x = *(uint32_t*)&pa; st.y = *(uint32_t*)&pb;
                *(uint2*)(smc + SV_B + ((vd0+dd)*FH + vj0)*2) = st;
            }
        }
        cp_wait0();
        __syncthreads();

        // ---- QK: warp tile 32x32 at (wm*32, wn*32), 8 k16-steps ----
        float sc[2][4][4];
#pragma unroll
        for (int i = 0; i < 2; i++)
#pragma unroll
            for (int j = 0; j < 4; j++)
                sc[i][j][0]=sc[i][j][1]=sc[i][j][2]=sc[i][j][3]=0.f;

        const uint32_t aQ0 = smb + (uint32_t)(SQ_B + (wm*32)*FH*2) + lmoff;
        const uint32_t bK0 = smb + (uint32_t)(SK_B + (wn*32)*FH*2) + lmoff;
#pragma unroll
        for (int ks = 0; ks < 8; ks++) {
            const uint32_t kk2 = (uint32_t)(ks*32);
            uint32_t qa[2][4], kb[4][2];
            LDSM4(qa[0][0], qa[0][1], qa[0][2], qa[0][3], aQ0 + kk2);
            LDSM4(qa[1][0], qa[1][1], qa[1][2], qa[1][3],
                  aQ0 + (uint32_t)(16*FH*2) + kk2);
            LDSM4(kb[0][0], kb[1][0], kb[0][1], kb[1][1], bK0 + kk2);
            LDSM4(kb[2][0], kb[3][0], kb[2][1], kb[3][1],
                  bK0 + (uint32_t)(16*FH*2) + kk2);
#pragma unroll
            for (int i = 0; i < 2; i++)
#pragma unroll
                for (int j = 0; j < 4; j++)
                    mma_f16(sc[i][j], qa[i], kb[j]);
        }

        // ---- register-resident softmax ----
        const int col0 = jb * 128;
        if (jb == qb) {
#pragma unroll
            for (int i = 0; i < 2; i++) {
                int rg = grow0 + wm*32 + i*16 + qd;
#pragma unroll
                for (int j = 0; j < 4; j++) {
                    int cg = col0 + wn*32 + j*8 + 2*r4;
                    if (cg     > rg)     sc[i][j][0] = -1e30f;
                    if (cg + 1 > rg)     sc[i][j][1] = -1e30f;
                    if (cg     > rg + 8) sc[i][j][2] = -1e30f;
                    if (cg + 1 > rg + 8) sc[i][j][3] = -1e30f;
                }
            }
        }
        // local row max + quad reduce + cross-warp partials
#pragma unroll
        for (int i = 0; i < 2; i++) {
            float mx0 = sc[i][0][0], mx1 = sc[i][0][2];
#pragma unroll
            for (int j = 0; j < 4; j++) {
                mx0 = fmaxf(mx0, fmaxf(sc[i][j][0], sc[i][j][1]));
                mx1 = fmaxf(mx1, fmaxf(sc[i][j][2], sc[i][j][3]));
            }
            mx0 = fmaxf(mx0, __shfl_xor_sync(0xffffffffu, mx0, 1));
            mx0 = fmaxf(mx0, __shfl_xor_sync(0xffffffffu, mx0, 2));
            mx1 = fmaxf(mx1, __shfl_xor_sync(0xffffffffu, mx1, 1));
            mx1 = fmaxf(mx1, __shfl_xor_sync(0xffffffffu, mx1, 2));
            if (r4 == 0) {
                sRed[(wm*32 + i*16 + qd)*4 + wn]     = mx0;
                sRed[(wm*32 + i*16 + qd + 8)*4 + wn] = mx1;
            }
        }
        __syncthreads();
        float corr[4];
#pragma unroll
        for (int i = 0; i < 2; i++)
#pragma unroll
            for (int hh = 0; hh < 2; hh++) {
                int row = wm*32 + i*16 + qd + hh*8;
                float4 rv = *(float4*)&sRed[row*4];
                float mt = fmaxf(fmaxf(rv.x, rv.y), fmaxf(rv.z, rv.w));
                int ix = i*2 + hh;
                float mn = fmaxf(m_r[ix], mt);
                corr[ix] = __expf(m_r[ix] - mn);
                m_r[ix] = mn;
            }
        float lsum[4] = {0.f, 0.f, 0.f, 0.f};
#pragma unroll
        for (int i = 0; i < 2; i++) {
            const int rowA = wm*32 + i*16 + qd;
#pragma unroll
            for (int j = 0; j < 4; j++) {
                const int col = wn*32 + j*8 + 2*r4;
                float p0 = __expf(sc[i][j][0] - m_r[i*2]);
                float p1 = __expf(sc[i][j][1] - m_r[i*2]);
                float p2 = __expf(sc[i][j][2] - m_r[i*2+1]);
                float p3 = __expf(sc[i][j][3] - m_r[i*2+1]);
                lsum[i*2]   += p0 + p1;
                lsum[i*2+1] += p2 + p3;
                *(__half2*)&sP[rowA*FH + col]     = __floats2half2_rn(p0, p1);
                *(__half2*)&sP[(rowA+8)*FH + col] = __floats2half2_rn(p2, p3);
            }
        }
#pragma unroll
        for (int ix = 0; ix < 4; ix++) {
            lsum[ix] += __shfl_xor_sync(0xffffffffu, lsum[ix], 1);
            lsum[ix] += __shfl_xor_sync(0xffffffffu, lsum[ix], 2);
        }
        if (r4 == 0) {
#pragma unroll
            for (int i = 0; i < 2; i++) {
                sRed2[(wm*32 + i*16 + qd)*4 + wn]     = lsum[i*2];
                sRed2[(wm*32 + i*16 + qd + 8)*4 + wn] = lsum[i*2+1];
            }
        }
        __syncthreads();
#pragma unroll
        for (int i = 0; i < 2; i++)
#pragma unroll
            for (int hh = 0; hh < 2; hh++) {
                int row = wm*32 + i*16 + qd + hh*8;
                float4 sv = *(float4*)&sRed2[row*4];
                int ix = i*2 + hh;
                l_r[ix] = l_r[ix]*corr[ix] + (sv.x + sv.y) + (sv.z + sv.w);
            }
#pragma unroll
        for (int i = 0; i < 2; i++)
#pragma unroll
            for (int j = 0; j < 4; j++) {
                oacc[i][j][0] *= corr[i*2];   oacc[i][j][1] *= corr[i*2];
                oacc[i][j][2] *= corr[i*2+1]; oacc[i][j][3] *= corr[i*2+1];
            }

        // ---- PV: warp tile 32x32, 8 k16-steps (A = P fp16, B = Vt fp16) ----
        const uint32_t aS0 = smb + (uint32_t)(SP_B + (wm*32)*FH*2) + lmoff;
        const uint32_t bV0 = smb + (uint32_t)(SV_B + (wn*32)*FH*2) + lmoff;
#pragma unroll
        for (int ks = 0; ks < 8; ks++) {
            const uint32_t kk2 = (uint32_t)(ks*32);
            uint32_t pa[2][4], vb[4][2];
            LDSM4(pa[0][0], pa[0][1], pa[0][2], pa[0][3], aS0 + kk2);
            LDSM4(pa[1][0], pa[1][1], pa[1][2], pa[1][3],
                  aS0 + (uint32_t)(16*FH*2) + kk2);
            LDSM4(vb[0][0], vb[1][0], vb[0][1], vb[1][1], bV0 + kk2);
            LDSM4(vb[2][0], vb[3][0], vb[2][1], vb[3][1],
                  bV0 + (uint32_t)(16*FH*2) + kk2);
#pragma unroll
            for (int i = 0; i < 2; i++)
#pragma unroll
                for (int j = 0; j < 4; j++)
                    mma_f16(oacc[i][j], pa[i], vb[j]);
        }
    }

    // epilogue: normalize, store fp16 ctx
#pragma unroll
    for (int i = 0; i < 2; i++) {
        const float inv0 = 1.f / l_r[i*2];
        const float inv1 = 1.f / l_r[i*2+1];
        const int row = wm*32 + i*16 + qd;
        __half* d0 = ctx + ((size_t)(b*SEQ + grow0 + row  ) * NH + h) * HD;
        __half* d1 = ctx + ((size_t)(b*SEQ + grow0 + row+8) * NH + h) * HD;
#pragma unroll
        for (int j = 0; j < 4; j++) {
            const int col = wn*32 + j*8 + 2*r4;
            *(__half2*)(d0 + col) = __floats2half2_rn(oacc[i][j][0]*inv0,
                                                      oacc[i][j][1]*inv0);
            *(__half2*)(d1 + col) = __floats2half2_rn(oacc[i][j][2]*inv1,
                                                      oacc[i][j][3]*inv1);
        }
    }
}

// ---------------------------------------------------------------------------
extern "C" void kernel_launch(void* const* d_in, const int* in_sizes, int n_in,
                              void* d_out, int out_size)
{
    const float* hs   = (const float*)d_in[0];
    const float* cosp = (const float*)d_in[1];
    const float* sinp = (const float*)d_in[2];
    const float* Wq   = (const float*)d_in[3];
    const float* Wk   = (const float*)d_in[4];
    const float* Wv   = (const float*)d_in[5];
    const float* Wo   = (const float*)d_in[6];
    float* out = (float*)d_out;

    __half *qkv, *ctx, *hs_h, *wqkv, *wo;
    cudaGetSymbolAddress((void**)&qkv,  g_qkv);
    cudaGetSymbolAddress((void**)&ctx,  g_ctx);
    cudaGetSymbolAddress((void**)&hs_h, g_hs);
    cudaGetSymbolAddress((void**)&wqkv, g_wqkv);
    cudaGetSymbolAddress((void**)&wo,   g_wo);

    cudaFuncSetAttribute(gemm_mma, cudaFuncAttributeMaxDynamicSharedMemorySize,
                         (int)GEMM_SMEM);
    cudaFuncSetAttribute(flash_mma_kernel, cudaFuncAttributeMaxDynamicSharedMemorySize,
                         (int)FLASH_SMEM);

    const int M = MTOT;  // 4096

    // 1) fp32 -> fp16 conversion of all inputs
    round5_kernel<<<(N4_TOT + 255)/256, 256>>>(hs, Wq, Wk, Wv, Wo,
                                               hs_h, wqkv, wo);

    // 2) fused QKV projection (fp16 MMA, fp16 output)
    gemm_mma<<<dim3(QKVW/256, M/128), 512, GEMM_SMEM>>>(hs_h, wqkv, qkv,
                                                        M, QKVW, HIDDEN, 1);

    // 3) fused RoPE on q (scaled) and k
    rope_kernel<<<(ROPE_TOT + 255)/256, 256>>>(qkv, cosp, sinp);

    // 4) attention (fp16, register softmax)
    flash_mma_kernel<<<dim3(SEQ/128, NH, BATCH), 512, FLASH_SMEM>>>(qkv, ctx);

    // 5) output projection (fp16 MMA, fp32 output)
    gemm_mma<<<dim3(HIDDEN/256, M/128), 512, GEMM_SMEM>>>(ctx, wo, out,
                                                          M, HIDDEN, HIDDEN, 0);
}

// round 14
// speedup vs baseline: 2.3730x; 1.6780x over previous
#include <cuda_runtime.h>
#include <cuda_fp16.h>
#include <math.h>
#include <stdint.h>

#define BATCH 2
#define SEQ 2048
#define HIDDEN 2048
#define NH 16
#define KVH 4
#define HD 128
#define MTOT (BATCH*SEQ)
#define QKVW 3072
#define KOFF 2048
#define VOFF 2560
#define SSCALE 0.08838834764831845f

// scratch (no allocation allowed -> device globals), all fp16
__device__ __align__(16) __half g_qkv[MTOT*QKVW];
__device__ __align__(16) __half g_ctx[MTOT*HIDDEN];
__device__ __align__(16) __half g_hs[MTOT*HIDDEN];
__device__ __align__(16) __half g_wqkv[QKVW*HIDDEN];
__device__ __align__(16) __half g_wo[HIDDEN*HIDDEN];

// ===========================================================================
// helpers
// ===========================================================================
__device__ __forceinline__ uint32_t smem_u32(const void* p) {
    uint32_t a;
    asm("{ .reg .u64 t; cvta.to.shared.u64 t, %1; cvt.u32.u64 %0, t; }"
        : "=r"(a) : "l"(p));
    return a;
}
__device__ __forceinline__ void cp_async16(uint32_t saddr, const void* gaddr) {
    asm volatile("cp.async.cg.shared.global [%0], [%1], 16;"
                 :: "r"(saddr), "l"(gaddr));
}
__device__ __forceinline__ void cp_commit() {
    asm volatile("cp.async.commit_group;" ::: "memory");
}
__device__ __forceinline__ void cp_wait2() {
    asm volatile("cp.async.wait_group 2;" ::: "memory");
}
__device__ __forceinline__ void cp_wait0() {
    asm volatile("cp.async.wait_group 0;" ::: "memory");
}
// D += A*B : fp16 m16n8k16, fp32 accumulate
__device__ __forceinline__ void mma_f16(float* d, const uint32_t* a, const uint32_t* b) {
    asm volatile(
        "mma.sync.aligned.m16n8k16.row.col.f32.f16.f16.f32 "
        "{%0,%1,%2,%3}, {%4,%5,%6,%7}, {%8,%9}, {%0,%1,%2,%3};"
        : "+f"(d[0]), "+f"(d[1]), "+f"(d[2]), "+f"(d[3])
        : "r"(a[0]), "r"(a[1]), "r"(a[2]), "r"(a[3]), "r"(b[0]), "r"(b[1]));
}
#define LDSM4(r0,r1,r2,r3,addr)                                              \
    asm volatile("ldmatrix.sync.aligned.m8n8.x4.shared.b16 {%0,%1,%2,%3}, [%4];" \
        : "=r"(r0), "=r"(r1), "=r"(r2), "=r"(r3) : "r"(addr))
#define LDSM4T(r0,r1,r2,r3,addr)                                             \
    asm volatile("ldmatrix.sync.aligned.m8n8.x4.trans.shared.b16 {%0,%1,%2,%3}, [%4];" \
        : "=r"(r0), "=r"(r1), "=r"(r2), "=r"(r3) : "r"(addr))

// ===========================================================================
// fused fp16 conversion pass: hs -> g_hs, [Wq|Wk|Wv] -> g_wqkv, Wo -> g_wo
// ===========================================================================
#define N4_HS  (MTOT*HIDDEN/4)
#define N4_WQ  (HIDDEN*HIDDEN/4)
#define N4_WKV (KVH*HD*HIDDEN/4)
#define N4_TOT (N4_HS + 2*N4_WQ + 2*N4_WKV)

__global__ void round5_kernel(
    const float* __restrict__ hs, const float* __restrict__ wq,
    const float* __restrict__ wk, const float* __restrict__ wv,
    const float* __restrict__ wo,
    __half* __restrict__ dhs, __half* __restrict__ dwqkv,
    __half* __restrict__ dwo)
{
    int i = blockIdx.x * 256 + threadIdx.x;
    if (i >= N4_TOT) return;
    const float* src; __half* dst; int j = i;
    if (j < N4_HS)                  { src = hs; dst = dhs; }
    else if ((j -= N4_HS) < N4_WQ)  { src = wq; dst = dwqkv; }
    else if ((j -= N4_WQ) < N4_WKV) { src = wk; dst = dwqkv + (size_t)KOFF*HIDDEN; }
    else if ((j -= N4_WKV) < N4_WKV){ src = wv; dst = dwqkv + (size_t)VOFF*HIDDEN; }
    else { j -= N4_WKV; src = wo; dst = dwo; }
    float4 v = ((const float4*)src)[j];
    ((__half2*)dst)[2*j]   = __floats2half2_rn(v.x, v.y);
    ((__half2*)dst)[2*j+1] = __floats2half2_rn(v.z, v.w);
}

// ===========================================================================
// fp16 mma.sync GEMM with ldmatrix. CTA 128x256, BK=64 halves, 4-stage
// cp.async, 512 threads (16 warps, 2x8 grid, warp tile 64x32).
// ===========================================================================
#define BKH 64
#define APADH 72
#define STAGE_HALVES ((128+256)*APADH)
#define NSTAGE 4
#define GEMM_SMEM (NSTAGE*STAGE_HALVES*2)

__global__ void __launch_bounds__(512, 1) gemm_mma(
    const __half* __restrict__ A, const __half* __restrict__ B,
    void* __restrict__ Cv, int M, int N, int K, int store_half)
{
    extern __shared__ __half smh[];
    const uint32_t smb = smem_u32(smh);

    const int tid  = threadIdx.x;
    const int warp = tid >> 5, lane = tid & 31;
    const int wm = warp >> 3, wn = warp & 7;
    const int m0 = blockIdx.y << 7, n0 = blockIdx.x << 8;
    const int q = lane >> 2, r = lane & 3;

    const int lmt = lane >> 3, lmr = lane & 7;
    const uint32_t lmoff = (uint32_t)((((lmt & 1) << 3 | lmr) * APADH + ((lmt >> 1) << 3)) * 2);

    float acc[4][4][4];
#pragma unroll
    for (int i = 0; i < 4; i++)
#pragma unroll
        for (int j = 0; j < 4; j++)
            acc[i][j][0]=acc[i][j][1]=acc[i][j][2]=acc[i][j][3]=0.f;

    const int arow0 = tid >> 3, ach = (tid & 7) << 3;

#define LOAD_TILE(s, kt) do {                                               \
    const uint32_t sA_ = smb + (uint32_t)(s)*STAGE_HALVES*2;                \
    const uint32_t sB_ = sA_ + 128*APADH*2;                                 \
    const int koff = (kt) * BKH;                                            \
    _Pragma("unroll")                                                       \
    for (int l_ = 0; l_ < 2; l_++) {                                        \
        int row = arow0 + l_*64;                                            \
        cp_async16(sA_ + (uint32_t)(row*APADH + ach)*2,                     \
                   A + (size_t)(m0 + row) * K + koff + ach);                \
    }                                                                       \
    _Pragma("unroll")                                                       \
    for (int l_ = 0; l_ < 4; l_++) {                                        \
        int row = arow0 + l_*64;                                            \
        cp_async16(sB_ + (uint32_t)(row*APADH + ach)*2,                     \
                   B + (size_t)(n0 + row) * K + koff + ach);                \
    } } while (0)

    const int KT = K / BKH;
    LOAD_TILE(0, 0); cp_commit();
    LOAD_TILE(1, 1); cp_commit();
    LOAD_TILE(2, 2); cp_commit();
    cp_wait2();
    __syncthreads();

    for (int kt = 0; kt < KT; kt++) {
        const int nxt = kt + 3;
        if (nxt < KT) {
            LOAD_TILE(nxt & 3, nxt);
        }
        cp_commit();

        const int cs = kt & 3;
        const uint32_t sAb = smb + (uint32_t)cs*STAGE_HALVES*2;
        const uint32_t sBb = sAb + 128*APADH*2;

#pragma unroll
        for (int ks = 0; ks < 4; ks++) {
            const uint32_t kk2 = (uint32_t)(ks*32);
            uint32_t afr[4][4], bfr[4][2];
#pragma unroll
            for (int i = 0; i < 4; i++)
                LDSM4(afr[i][0], afr[i][1], afr[i][2], afr[i][3],
                      sAb + (uint32_t)((wm*64 + i*16)*APADH*2) + lmoff + kk2);
            LDSM4(bfr[0][0], bfr[1][0], bfr[0][1], bfr[1][1],
                  sBb + (uint32_t)((wn*32)*APADH*2) + lmoff + kk2);
            LDSM4(bfr[2][0], bfr[3][0], bfr[2][1], bfr[3][1],
                  sBb + (uint32_t)((wn*32 + 16)*APADH*2) + lmoff + kk2);
#pragma unroll
            for (int i = 0; i < 4; i++)
#pragma unroll
                for (int j = 0; j < 4; j++)
                    mma_f16(acc[i][j], afr[i], bfr[j]);
        }

        cp_wait2();
        __syncthreads();
    }

    if (store_half) {
        __half* C = (__half*)Cv;
#pragma unroll
        for (int i = 0; i < 4; i++) {
            const int row = m0 + wm*64 + i*16 + q;
#pragma unroll
            for (int j = 0; j < 4; j++) {
                const int col = n0 + wn*32 + j*8 + 2*r;
                *(__half2*)(C + (size_t)row * N + col) =
                    __floats2half2_rn(acc[i][j][0], acc[i][j][1]);
                *(__half2*)(C + (size_t)(row+8) * N + col) =
                    __floats2half2_rn(acc[i][j][2], acc[i][j][3]);
            }
        }
    } else {
        float* C = (float*)Cv;
#pragma unroll
        for (int i = 0; i < 4; i++) {
            const int row = m0 + wm*64 + i*16 + q;
#pragma unroll
            for (int j = 0; j < 4; j++) {
                const int col = n0 + wn*32 + j*8 + 2*r;
                float2 lo; lo.x = acc[i][j][0]; lo.y = acc[i][j][1];
                float2 hi; hi.x = acc[i][j][2]; hi.y = acc[i][j][3];
                *(float2*)(C + (size_t)row * N + col)     = lo;
                *(float2*)(C + (size_t)(row+8) * N + col) = hi;
            }
        }
    }
#undef LOAD_TILE
}

// ---------------------------------------------------------------------------
// fused RoPE on fp16 q (with sscale folded) and k, in-place
// ---------------------------------------------------------------------------
#define ROPE_NQ (MTOT*NH*64)
#define ROPE_NK (MTOT*KVH*64)
#define ROPE_TOT (ROPE_NQ + ROPE_NK)

__global__ void rope_kernel(__half* __restrict__ qkv,
                            const float* __restrict__ cs,
                            const float* __restrict__ sn)
{
    int idx = blockIdx.x * 256 + threadIdx.x;
    if (idx < ROPE_NQ) {
        int d = idx & 63;
        int h = (idx >> 6) % NH;
        int t = idx / (NH << 6);
        __half* row = qkv + (size_t)t * QKVW + h * HD;
        int s = t & (SEQ - 1);
        float x1 = __half2float(row[d]), x2 = __half2float(row[d + 64]);
        row[d]      = __float2half((x1 * cs[s*HD + d]      - x2 * sn[s*HD + d])      * SSCALE);
        row[d + 64] = __float2half((x2 * cs[s*HD + d + 64] + x1 * sn[s*HD + d + 64]) * SSCALE);
    } else if ((idx -= ROPE_NQ) < ROPE_NK) {
        int d = idx & 63;
        int h = (idx >> 6) % KVH;
        int t = idx / (KVH << 6);
        __half* row = qkv + (size_t)t * QKVW + KOFF + h * HD;
        int s = t & (SEQ - 1);
        float x1 = __half2float(row[d]), x2 = __half2float(row[d + 64]);
        row[d]      = __float2half(x1 * cs[s*HD + d]      - x2 * sn[s*HD + d]);
        row[d + 64] = __float2half(x2 * cs[s*HD + d + 64] + x1 * sn[s*HD + d + 64]);
    }
}

// ---------------------------------------------------------------------------
// Flash attention v2 (FA2 layout): fp16 mma, register-resident P.
// Br=Bc=128, D=128. 256 threads, 8 warps; each warp owns 16 full rows.
// K/V double-buffered cp.async; V consumed via ldmatrix.trans.
// One __syncthreads per tile; softmax entirely warp-local.
// ---------------------------------------------------------------------------
#define FH 136
#define TILE_B (128*FH*2)                 // 34816 bytes
#define SQ_B 0
#define SK_B(s) (TILE_B*(1 + 2*(s)))
#define SV_B(s) (TILE_B*(2 + 2*(s)))
#define FLASH_SMEM (5*TILE_B)

__global__ void __launch_bounds__(256, 1) flash_mma_kernel(
    const __half* __restrict__ qkv, __half* __restrict__ ctx)
{
    extern __shared__ char smc[];
    const uint32_t smb = smem_u32(smc);

    const int b = blockIdx.z, h = blockIdx.y;
    const int qb = (int)gridDim.x - 1 - (int)blockIdx.x;   // long CTAs first
    const int kh = h >> 2;
    const int tid = threadIdx.x;
    const int warp = tid >> 5, lane = tid & 31;
    const int qd = lane >> 2, r4 = lane & 3;

    const int lmt = lane >> 3, lmr = lane & 7;
    // non-trans (A / K-as-B): row = n/m index, col = k offset
    const uint32_t lmoff  = (uint32_t)(((((lmt & 1) << 3) | lmr) * FH + ((lmt >> 1) << 3)) * 2);
    // trans (V as B): row = k (j) index, col = n (d) offset
    const uint32_t lmoffT = (uint32_t)(((lmr + ((lmt >> 1) << 3)) * FH + ((lmt & 1) << 3)) * 2);

    const int grow0 = qb * 128;

    // ---- prologue: Q + K0 + V0 in one group ----
    {
        const __half* qb_ = qkv + (size_t)(b*SEQ + qb*128) * QKVW + h * HD;
        const __half* kb_ = qkv + (size_t)(b*SEQ) * QKVW + KOFF + kh * HD;
        const __half* vb_ = qkv + (size_t)(b*SEQ) * QKVW + VOFF + kh * HD;
#pragma unroll
        for (int l = 0; l < 8; l++) {
            int idx = tid + l*256;
            int row = idx >> 4, ch = (idx & 15) << 3;
            uint32_t so = (uint32_t)((row*FH + ch)*2);
            cp_async16(smb + SQ_B    + so, qb_ + (size_t)row * QKVW + ch);
            cp_async16(smb + SK_B(0) + so, kb_ + (size_t)row * QKVW + ch);
            cp_async16(smb + SV_B(0) + so, vb_ + (size_t)row * QKVW + ch);
        }
        cp_commit();
    }

    float m_r0 = -1e30f, m_r1 = -1e30f, l_r0 = 0.f, l_r1 = 0.f;
    float oacc[16][4];
#pragma unroll
    for (int j = 0; j < 16; j++)
        oacc[j][0]=oacc[j][1]=oacc[j][2]=oacc[j][3]=0.f;

    for (int jb = 0; jb <= qb; jb++) {
        cp_wait0();
        __syncthreads();   // tile jb data visible to all; prior tile reads done

        // prefetch tile jb+1 into the other buffer (overlaps with compute)
        if (jb < qb) {
            const int nb = (jb + 1) & 1;
            const __half* kb_ = qkv + (size_t)(b*SEQ + (jb+1)*128) * QKVW + KOFF + kh * HD;
            const __half* vb_ = qkv + (size_t)(b*SEQ + (jb+1)*128) * QKVW + VOFF + kh * HD;
            const uint32_t skn = smb + (uint32_t)SK_B(nb);
            const uint32_t svn = smb + (uint32_t)SV_B(nb);
#pragma unroll
            for (int l = 0; l < 8; l++) {
                int idx = tid + l*256;
                int row = idx >> 4, ch = (idx & 15) << 3;
                uint32_t so = (uint32_t)((row*FH + ch)*2);
                cp_async16(skn + so, kb_ + (size_t)row * QKVW + ch);
                cp_async16(svn + so, vb_ + (size_t)row * QKVW + ch);
            }
            cp_commit();
        }

        const uint32_t sK = smb + (uint32_t)SK_B(jb & 1);
        const uint32_t sV = smb + (uint32_t)SV_B(jb & 1);

        // ---- QK: warp rows warp*16..+15 x all 128 cols ----
        float sc[16][4];
#pragma unroll
        for (int j = 0; j < 16; j++)
            sc[j][0]=sc[j][1]=sc[j][2]=sc[j][3]=0.f;

        const uint32_t aQ0 = smb + (uint32_t)(SQ_B + (warp*16)*FH*2) + lmoff;
#pragma unroll
        for (int ks = 0; ks < 8; ks++) {
            const uint32_t kk2 = (uint32_t)(ks*32);
            uint32_t qa[4];
            LDSM4(qa[0], qa[1], qa[2], qa[3], aQ0 + kk2);
#pragma unroll
            for (int jt = 0; jt < 8; jt++) {
                uint32_t kb2[2][2];
                LDSM4(kb2[0][0], kb2[1][0], kb2[0][1], kb2[1][1],
                      sK + (uint32_t)((jt*16)*FH*2) + lmoff + kk2);
                mma_f16(sc[jt*2],   qa, kb2[0]);
                mma_f16(sc[jt*2+1], qa, kb2[1]);
            }
        }

        // ---- causal mask ----
        const int col0 = jb * 128;
        if (jb == qb) {
            const int rg0 = grow0 + warp*16 + qd;
#pragma unroll
            for (int j = 0; j < 16; j++) {
                int cg = col0 + j*8 + 2*r4;
                if (cg     > rg0)     sc[j][0] = -1e30f;
                if (cg + 1 > rg0)     sc[j][1] = -1e30f;
                if (cg     > rg0 + 8) sc[j][2] = -1e30f;
                if (cg + 1 > rg0 + 8) sc[j][3] = -1e30f;
            }
        }

        // ---- warp-local softmax ----
        float mx0 = sc[0][0], mx1 = sc[0][2];
#pragma unroll
        for (int j = 0; j < 16; j++) {
            mx0 = fmaxf(mx0, fmaxf(sc[j][0], sc[j][1]));
            mx1 = fmaxf(mx1, fmaxf(sc[j][2], sc[j][3]));
        }
        mx0 = fmaxf(mx0, __shfl_xor_sync(0xffffffffu, mx0, 1));
        mx0 = fmaxf(mx0, __shfl_xor_sync(0xffffffffu, mx0, 2));
        mx1 = fmaxf(mx1, __shfl_xor_sync(0xffffffffu, mx1, 1));
        mx1 = fmaxf(mx1, __shfl_xor_sync(0xffffffffu, mx1, 2));
        const float mn0 = fmaxf(m_r0, mx0);
        const float mn1 = fmaxf(m_r1, mx1);
        const float corr0 = __expf(m_r0 - mn0);
        const float corr1 = __expf(m_r1 - mn1);
        m_r0 = mn0; m_r1 = mn1;

        float ls0 = 0.f, ls1 = 0.f;
#pragma unroll
        for (int j = 0; j < 16; j++) {
            sc[j][0] = __expf(sc[j][0] - mn0); ls0 += sc[j][0];
            sc[j][1] = __expf(sc[j][1] - mn0); ls0 += sc[j][1];
            sc[j][2] = __expf(sc[j][2] - mn1); ls1 += sc[j][2];
            sc[j][3] = __expf(sc[j][3] - mn1); ls1 += sc[j][3];
        }
        ls0 += __shfl_xor_sync(0xffffffffu, ls0, 1);
        ls0 += __shfl_xor_sync(0xffffffffu, ls0, 2);
        ls1 += __shfl_xor_sync(0xffffffffu, ls1, 1);
        ls1 += __shfl_xor_sync(0xffffffffu, ls1, 2);
        l_r0 = l_r0 * corr0 + ls0;
        l_r1 = l_r1 * corr1 + ls1;
#pragma unroll
        for (int j = 0; j < 16; j++) {
            oacc[j][0] *= corr0; oacc[j][1] *= corr0;
            oacc[j][2] *= corr1; oacc[j][3] *= corr1;
        }

        // ---- PV: A = P (in registers, converted), B = V via ldmatrix.trans ----
#pragma unroll
        for (int c = 0; c < 8; c++) {
            uint32_t pa[4];
            {
                __half2 t0 = __floats2half2_rn(sc[2*c][0],   sc[2*c][1]);
                __half2 t1 = __floats2half2_rn(sc[2*c][2],   sc[2*c][3]);
                __half2 t2 = __floats2half2_rn(sc[2*c+1][0], sc[2*c+1][1]);
                __half2 t3 = __floats2half2_rn(sc[2*c+1][2], sc[2*c+1][3]);
                pa[0] = *(uint32_t*)&t0; pa[1] = *(uint32_t*)&t1;
                pa[2] = *(uint32_t*)&t2; pa[3] = *(uint32_t*)&t3;
            }
            const uint32_t vrow = sV + (uint32_t)((c*16)*FH*2) + lmoffT;
#pragma unroll
            for (int dt = 0; dt < 8; dt++) {
                uint32_t vb2[2][2];
                LDSM4T(vb2[0][0], vb2[1][0], vb2[0][1], vb2[1][1],
                       vrow + (uint32_t)((dt*16)*2));
                mma_f16(oacc[dt*2],   pa, vb2[0]);
                mma_f16(oacc[dt*2+1], pa, vb2[1]);
            }
        }
    }

    // ---- epilogue: normalize, store fp16 ctx ----
    const float inv0 = 1.f / l_r0;
    const float inv1 = 1.f / l_r1;
    const int row = warp*16 + qd;
    __half* d0 = ctx + ((size_t)(b*SEQ + grow0 + row  ) * NH + h) * HD;
    __half* d1 = ctx + ((size_t)(b*SEQ + grow0 + row+8) * NH + h) * HD;
#pragma unroll
    for (int j = 0; j < 16; j++) {
        const int col = j*8 + 2*r4;
        *(__half2*)(d0 + col) = __floats2half2_rn(oacc[j][0]*inv0, oacc[j][1]*inv0);
        *(__half2*)(d1 + col) = __floats2half2_rn(oacc[j][2]*inv1, oacc[j][3]*inv1);
    }
}

// ---------------------------------------------------------------------------
extern "C" void kernel_launch(void* const* d_in, const int* in_sizes, int n_in,
                              void* d_out, int out_size)
{
    const float* hs   = (const float*)d_in[0];
    const float* cosp = (const float*)d_in[1];
    const float* sinp = (const float*)d_in[2];
    const float* Wq   = (const float*)d_in[3];
    const float* Wk   = (const float*)d_in[4];
    const float* Wv   = (const float*)d_in[5];
    const float* Wo   = (const float*)d_in[6];
    float* out = (float*)d_out;

    __half *qkv, *ctx, *hs_h, *wqkv, *wo;
    cudaGetSymbolAddress((void**)&qkv,  g_qkv);
    cudaGetSymbolAddress((void**)&ctx,  g_ctx);
    cudaGetSymbolAddress((void**)&hs_h, g_hs);
    cudaGetSymbolAddress((void**)&wqkv, g_wqkv);
    cudaGetSymbolAddress((void**)&wo,   g_wo);

    cudaFuncSetAttribute(gemm_mma, cudaFuncAttributeMaxDynamicSharedMemorySize,
                         (int)GEMM_SMEM);
    cudaFuncSetAttribute(flash_mma_kernel, cudaFuncAttributeMaxDynamicSharedMemorySize,
                         (int)FLASH_SMEM);

    const int M = MTOT;  // 4096

    // 1) fp32 -> fp16 conversion of all inputs
    round5_kernel<<<(N4_TOT + 255)/256, 256>>>(hs, Wq, Wk, Wv, Wo,
                                               hs_h, wqkv, wo);

    // 2) fused QKV projection (fp16 MMA, fp16 output)
    gemm_mma<<<dim3(QKVW/256, M/128), 512, GEMM_SMEM>>>(hs_h, wqkv, qkv,
                                                        M, QKVW, HIDDEN, 1);

    // 3) fused RoPE on q (scaled) and k
    rope_kernel<<<(ROPE_TOT + 255)/256, 256>>>(qkv, cosp, sinp);

    // 4) attention (FA2 layout: register P, warp-local softmax, dbuf K/V)
    flash_mma_kernel<<<dim3(SEQ/128, NH, BATCH), 256, FLASH_SMEM>>>(qkv, ctx);

    // 5) output projection (fp16 MMA, fp32 output)
    gemm_mma<<<dim3(HIDDEN/256, M/128), 512, GEMM_SMEM>>>(ctx, wo, out,
                                                          M, HIDDEN, HIDDEN, 0);
}